// round 15
// baseline (speedup 1.0000x reference)
#include <cuda_runtime.h>
#include <cuda_bf16.h>
#include <cuda_fp16.h>
#include <math.h>
#include <stdint.h>

#define B_    4
#define C_    384
#define H_    224
#define HH_   28
#define N_    784
#define HEADS 8
#define HD    48
#define R3C   (3 * C_)

#define AFF_SCALE  0.05103103630798288f   /* 384^-0.5 */
#define ATTN_SCALE 0.14433756729740643f   /* 48^-0.5 */
#define LOG2E      1.4426950408889634f

typedef unsigned long long ull;
typedef __nv_bfloat16 bf16;

__device__ __forceinline__ ull pk2(float a, float b) {
    ull r;
    asm("mov.b64 %0, {%1, %2};" : "=l"(r) : "f"(a), "f"(b));
    return r;
}
__device__ __forceinline__ void upk2(ull v, float& a, float& b) {
    asm("mov.b64 {%0, %1}, %2;" : "=f"(a), "=f"(b) : "l"(v));
}
#define FMA2(d, a, b) asm("fma.rn.f32x2 %0, %1, %2, %0;" : "+l"(d) : "l"(a), "l"(b))

__device__ __forceinline__ uint32_t smem_u32(const void* p) {
    uint32_t a;
    asm("{ .reg .u64 t; cvta.to.shared.u64 t, %1; cvt.u32.u64 %0, t; }" : "=r"(a) : "l"(p));
    return a;
}
__device__ __forceinline__ uint32_t pk_bf(bf16 a, bf16 b) {
    uint16_t ra = *(uint16_t*)&a, rb = *(uint16_t*)&b;
    return (uint32_t)ra | ((uint32_t)rb << 16);
}
__device__ __forceinline__ void split_bf(float f, bf16& h, bf16& l) {
    h = __float2bfloat16_rn(f);
    l = __float2bfloat16_rn(f - __bfloat162float(h));
}
__device__ __forceinline__ void split_h(float f, __half& h, __half& l) {
    h = __float2half_rn(f);
    l = __float2half_rn(f - __half2float(h));
}
__device__ __forceinline__ uint32_t cvt_h2(float a, float b) {
    uint32_t r;
    asm("cvt.rn.f16x2.f32 %0, %1, %2;" : "=r"(r) : "f"(b), "f"(a));
    return r;
}
__device__ __forceinline__ uint32_t ex2_h2(uint32_t x) {
    uint32_t r;
    asm("ex2.approx.f16x2 %0, %1;" : "=r"(r) : "r"(x));
    return r;
}
__device__ __forceinline__ uint32_t addh2(uint32_t a, uint32_t b) {
    uint32_t r;
    asm("add.f16x2 %0, %1, %2;" : "=r"(r) : "r"(a), "r"(b));
    return r;
}
__device__ __forceinline__ float h2sum(uint32_t v) {
    __half2 h = *(__half2*)&v;
    return __low2float(h) + __high2float(h);
}

#define LDSM4(r, addr) \
    asm volatile("ldmatrix.sync.aligned.m8n8.x4.shared.b16 {%0,%1,%2,%3}, [%4];" \
                 : "=r"((r)[0]), "=r"((r)[1]), "=r"((r)[2]), "=r"((r)[3]) : "r"(addr))
#define LDSM2(r, addr) \
    asm volatile("ldmatrix.sync.aligned.m8n8.x2.shared.b16 {%0,%1}, [%2];" \
                 : "=r"((r)[0]), "=r"((r)[1]) : "r"(addr))
#define MMA16816(d, a, b) \
    asm volatile("mma.sync.aligned.m16n8k16.row.col.f32.bf16.bf16.f32 " \
                 "{%0,%1,%2,%3}, {%4,%5,%6,%7}, {%8,%9}, {%0,%1,%2,%3};" \
                 : "+f"((d)[0]), "+f"((d)[1]), "+f"((d)[2]), "+f"((d)[3]) \
                 : "r"((a)[0]), "r"((a)[1]), "r"((a)[2]), "r"((a)[3]), \
                   "r"((b)[0]), "r"((b)[1]))
#define MMA16816H(d, a, b) \
    asm volatile("mma.sync.aligned.m16n8k16.row.col.f32.f16.f16.f32 " \
                 "{%0,%1,%2,%3}, {%4,%5,%6,%7}, {%8,%9}, {%0,%1,%2,%3};" \
                 : "+f"((d)[0]), "+f"((d)[1]), "+f"((d)[2]), "+f"((d)[3]) \
                 : "r"((a)[0]), "r"((a)[1]), "r"((a)[2]), "r"((a)[3]), \
                   "r"((b)[0]), "r"((b)[1]))

__device__ __forceinline__ void cpa16(uint32_t saddr, const void* g) {
    asm volatile("cp.async.cg.shared.global [%0], [%1], 16;" :: "r"(saddr), "l"(g));
}
#define CPA_COMMIT() asm volatile("cp.async.commit_group;" ::: "memory")
#define CPA_WAIT(n)  asm volatile("cp.async.wait_group %0;" :: "n"(n) : "memory")

// ------------------------- scratch (device globals, no allocs) -------------
__device__ float g_sf[B_ * N_ * C_];
__device__ float g_aff[B_ * N_ * 64 * 9];
__device__ float g_affsum[B_ * N_ * 9];
__device__ float g_sft_site[B_ * N_ * 9 * C_];
__device__ float g_sftn[B_ * N_ * C_];
__device__ float g_qkv[B_ * R3C * N_];
__device__ float g_attno[B_ * N_ * C_];
__device__ float g_projo[B_ * N_ * C_];
__device__ bf16 g_qkvw_h[R3C * C_], g_qkvw_l[R3C * C_];
__device__ bf16 g_projw_h[C_ * C_], g_projw_l[C_ * C_];

// ------------------------- 0) split weights --------------------------------
__global__ void split_w(const float* __restrict__ qkv_w, const float* __restrict__ proj_w) {
    int idx = blockIdx.x * 256 + threadIdx.x;
    for (int i = idx; i < R3C * C_; i += gridDim.x * 256) {
        bf16 h, l;
        split_bf(qkv_w[i], h, l);
        g_qkvw_h[i] = h;
        g_qkvw_l[i] = l;
    }
    for (int i = idx; i < C_ * C_; i += gridDim.x * 256) {
        bf16 h, l;
        split_bf(proj_w[i], h, l);
        g_projw_h[i] = h;
        g_projw_l[i] = l;
    }
}

// ------------------------- 1) 8x8 average pool (float4) --------------------
__global__ void pool_kernel(const float* __restrict__ xs) {
    int y = blockIdx.x, c = blockIdx.y, b = blockIdx.z;
    int t = threadIdx.x;
    int r = t / 28, xx = t - r * 28;
    const float* base = xs + ((size_t)(b * C_ + c) * H_ + (size_t)y * 8) * H_;
    float4 a = *(const float4*)(base + (size_t)r * H_ + xx * 8);
    float4 d = *(const float4*)(base + (size_t)r * H_ + xx * 8 + 4);
    float partial = (a.x + a.y) + (a.z + a.w) + (d.x + d.y) + (d.z + d.w);
    __shared__ float sm[224];
    sm[r * 28 + xx] = partial;
    __syncthreads();
    if (t < HH_) {
        float acc = 0.f;
#pragma unroll
        for (int i = 0; i < 8; i++) acc += sm[i * 28 + t];
        g_sf[((size_t)b * N_ + (size_t)y * HH_ + t) * C_ + c] = acc * (1.0f / 64.0f);
    }
}

// ------------------------- 2) site kernel v5: 4-wide amortized loops -------
#define CK 96
#define PIXPAD 68
#define BUF_F (CK * PIXPAD)              /* 6528 */
#define S_SF9  (4 * BUF_F)               /* 26112 */
#define S_STG  (S_SF9 + C_ * 10)         /* 29952 */
#define S_AFF  (S_STG + 13824)           /* 43776 */
#define SITE_SMEM_FLOATS (S_AFF + 640)   /* 44416 floats = 177664 B */

__global__ __launch_bounds__(384, 1) void site_kernel(const float* __restrict__ xs) {
    extern __shared__ __align__(16) float sm[];
    float* sf9   = sm + S_SF9;
    float* stg   = sm + S_STG;
    float* aff_s = sm + S_AFF;

    int n = blockIdx.x, b = blockIdx.y;
    int y = n / HH_, x = n % HH_;
    int tid = threadIdx.x;
    const float* xbase = xs + ((size_t)b * C_ * H_ + (size_t)y * 8) * H_ + (size_t)x * 8;

    // issue chunk 0
    for (int i = tid; i < CK * 16; i += 384) {
        int cl = i >> 4, r = i & 15;
        int py = r >> 1, px4 = (r & 1) << 2;
        cpa16(smem_u32(&sm[cl * PIXPAD + py * 8 + px4]),
              xbase + ((size_t)cl * H_ + py) * H_ + px4);
    }
    CPA_COMMIT();

#pragma unroll
    for (int k = 0; k < 9; k++) {
        int yy = y + k / 3 - 1, xx = x + k % 3 - 1;
        float v = 0.f;
        if (yy >= 0 && yy < HH_ && xx >= 0 && xx < HH_)
            v = g_sf[((size_t)b * N_ + yy * HH_ + xx) * C_ + tid];
        sf9[tid * 10 + k] = v;
    }

    // ---- phase A: logits. thread = (plane 0..15 -> pixel quad, csub 0..23 -> 4 ch)
    int plane = tid & 15, csub = tid >> 4;
    int p0 = plane * 4;
    ull lacc[4][4];
    float lacc8[4];
#pragma unroll
    for (int i = 0; i < 4; i++) {
        lacc8[i] = 0.f;
#pragma unroll
        for (int q = 0; q < 4; q++) lacc[i][q] = 0ull;
    }
    for (int ck = 0; ck < 4; ck++) {
        if (ck < 3) {
            float* nb = sm + (ck + 1) * BUF_F;
            int cbase = (ck + 1) * CK;
            for (int i = tid; i < CK * 16; i += 384) {
                int cl = i >> 4, r = i & 15;
                int py = r >> 1, px4 = (r & 1) << 2;
                cpa16(smem_u32(&nb[cl * PIXPAD + py * 8 + px4]),
                      xbase + ((size_t)(cbase + cl) * H_ + py) * H_ + px4);
            }
            CPA_COMMIT();
            CPA_WAIT(1);
        } else {
            CPA_WAIT(0);
        }
        __syncthreads();
        const float* buf = sm + ck * BUF_F;
#pragma unroll
        for (int cc = 0; cc < 4; cc++) {
            int cl = csub * 4 + cc;
            float4 pv4 = *(const float4*)&buf[cl * PIXPAD + p0];
            float pv[4] = {pv4.x, pv4.y, pv4.z, pv4.w};
            const float* s9 = &sf9[(ck * CK + cl) * 10];
            ull s01 = *(const ull*)(s9 + 0);
            ull s23 = *(const ull*)(s9 + 2);
            ull s45 = *(const ull*)(s9 + 4);
            ull s67 = *(const ull*)(s9 + 6);
            float s8 = s9[8];
#pragma unroll
            for (int i = 0; i < 4; i++) {
                ull pp = pk2(pv[i], pv[i]);
                FMA2(lacc[i][0], pp, s01);
                FMA2(lacc[i][1], pp, s23);
                FMA2(lacc[i][2], pp, s45);
                FMA2(lacc[i][3], pp, s67);
                lacc8[i] = fmaf(pv[i], s8, lacc8[i]);
            }
        }
    }
    // stage 24 partial buffers [csub][p][k]
#pragma unroll
    for (int i = 0; i < 4; i++) {
        float l[9];
        upk2(lacc[i][0], l[0], l[1]);
        upk2(lacc[i][1], l[2], l[3]);
        upk2(lacc[i][2], l[4], l[5]);
        upk2(lacc[i][3], l[6], l[7]);
        l[8] = lacc8[i];
#pragma unroll
        for (int k = 0; k < 9; k++) stg[csub * 576 + (p0 + i) * 9 + k] = l[k];
    }
    __syncthreads();
    for (int idx = tid; idx < 576; idx += 384) {
        float s = 0.f;
#pragma unroll
        for (int ch = 0; ch < 24; ch++) s += stg[ch * 576 + idx];
        int pp = idx / 9, k = idx - pp * 9;
        aff_s[pp * 10 + k] = s * AFF_SCALE;
    }
    __syncthreads();
    if (tid < 64) {
        float m = -1e30f;
#pragma unroll
        for (int k = 0; k < 9; k++) m = fmaxf(m, aff_s[tid * 10 + k]);
        float e[9], ssum = 0.f;
#pragma unroll
        for (int k = 0; k < 9; k++) { e[k] = __expf(aff_s[tid * 10 + k] - m); ssum += e[k]; }
        float inv = 1.f / ssum;
#pragma unroll
        for (int k = 0; k < 9; k++) aff_s[tid * 10 + k] = e[k] * inv;
    }
    __syncthreads();
    size_t abase = ((size_t)b * N_ + n) * 576;
    for (int idx = tid; idx < 576; idx += 384) {
        int pp = idx / 9, k = idx - pp * 9;
        g_aff[abase + idx] = aff_s[pp * 10 + k];
    }
    if (tid < 9) {
        float s = 0.f;
        for (int pp = 0; pp < 64; pp++) s += aff_s[pp * 10 + tid];
        g_affsum[((size_t)b * N_ + n) * 9 + tid] = s;
    }

    // ---- phase B: aggregation. thread = (cidx 0..23 -> 4 ch, psub 0..15 -> pixel quad)
    int cidx = tid % 24, psub = tid / 24;
    int pb = psub * 4;
    size_t sbase = ((size_t)b * N_ + n) * 9;
    for (int ck = 0; ck < 4; ck++) {
        const float* buf = sm + ck * BUF_F;
        // preload pixel quads for the 4 channels
        float pv[4][4];
#pragma unroll
        for (int j = 0; j < 4; j++) {
            int cl = cidx + 24 * j;
            float4 v = *(const float4*)&buf[cl * PIXPAD + pb];
            pv[j][0] = v.x; pv[j][1] = v.y; pv[j][2] = v.z; pv[j][3] = v.w;
        }
        ull a2[4][4];
        float a8[4];
#pragma unroll
        for (int j = 0; j < 4; j++) {
            a8[j] = 0.f;
#pragma unroll
            for (int q = 0; q < 4; q++) a2[j][q] = 0ull;
        }
#pragma unroll
        for (int pi = 0; pi < 4; pi++) {
            const float* a9 = &aff_s[(pb + pi) * 10];
            ull a01 = *(const ull*)(a9 + 0);
            ull a23 = *(const ull*)(a9 + 2);
            ull a45 = *(const ull*)(a9 + 4);
            ull a67 = *(const ull*)(a9 + 6);
            float av8 = a9[8];
#pragma unroll
            for (int j = 0; j < 4; j++) {
                ull pd = pk2(pv[j][pi], pv[j][pi]);
                FMA2(a2[j][0], pd, a01);
                FMA2(a2[j][1], pd, a23);
                FMA2(a2[j][2], pd, a45);
                FMA2(a2[j][3], pd, a67);
                a8[j] = fmaf(pv[j][pi], av8, a8[j]);
            }
        }
        __syncthreads();   // stg free (prev chunk reduce done)
#pragma unroll
        for (int j = 0; j < 4; j++) {
            float r[9];
            upk2(a2[j][0], r[0], r[1]);
            upk2(a2[j][1], r[2], r[3]);
            upk2(a2[j][2], r[4], r[5]);
            upk2(a2[j][3], r[6], r[7]);
            r[8] = a8[j];
            int cl = cidx + 24 * j;
#pragma unroll
            for (int k = 0; k < 9; k++) stg[psub * 864 + k * 96 + cl] = r[k];
        }
        __syncthreads();
        for (int idx = tid; idx < 864; idx += 384) {
            float s = 0.f;
#pragma unroll
            for (int ps = 0; ps < 16; ps++) s += stg[ps * 864 + idx];
            int k = idx / 96, cl = idx - k * 96;
            g_sft_site[(sbase + k) * C_ + ck * CK + cl] = s;
        }
        __syncthreads();
    }
}

// ------------------------- 3) fold3 gather + normalize ---------------------
__global__ void gather_kernel() {
    int n = blockIdx.x, b = blockIdx.y;
    int y = n / HH_, x = n % HH_;
    int c = threadIdx.x;
    float acc = 0.f, asum = 0.f;
#pragma unroll
    for (int k = 0; k < 9; k++) {
        int i = k / 3, j = k % 3;
        int sy = y + 1 - i, sx = x + 1 - j;
        if (sy >= 0 && sy < HH_ && sx >= 0 && sx < HH_) {
            size_t sb = ((size_t)b * N_ + sy * HH_ + sx) * 9 + k;
            acc += g_sft_site[sb * C_ + c];
            asum += g_affsum[sb];
        }
    }
    g_sftn[((size_t)b * N_ + n) * C_ + c] = acc / (asum + 1e-12f);
}

// ------------------------- 4/6) mma.sync GEMM (pre-split weights) ----------
#define SGA 72
#define GEMM_DSMEM (4 * 128 * SGA * 2)
__device__ __forceinline__ int ssw(int m, int n) { return m * 128 + (n ^ (((m >> 2) & 7) << 2)); }

template <bool TRANS_OUT>
__global__ __launch_bounds__(256, 2) void gemm_mma(const float* __restrict__ bias, int R1) {
    extern __shared__ __align__(16) char dyn[];
    bf16* Ah = (bf16*)dyn;
    bf16* Al = Ah + 128 * SGA;
    bf16* Xh = Al + 128 * SGA;
    bf16* Xl = Xh + 128 * SGA;

    int b = blockIdx.z;
    int obase = blockIdx.y * 128;
    int nbase = blockIdx.x * 128;
    int tid = threadIdx.x;
    int lane = tid & 31, w = tid >> 5;
    int wm = w & 3, wn = w >> 2;
    const bf16* Awh = TRANS_OUT ? g_projw_h : g_qkvw_h;
    const bf16* Awl = TRANS_OUT ? g_projw_l : g_qkvw_l;
    const float* X = (TRANS_OUT ? g_attno : g_sftn) + (size_t)b * N_ * C_;

    uint32_t baAh = smem_u32(Ah), baAl = smem_u32(Al);
    uint32_t baXh = smem_u32(Xh), baXl = smem_u32(Xl);

    float acc[2][8][4];
#pragma unroll
    for (int i = 0; i < 2; i++)
#pragma unroll
        for (int j = 0; j < 8; j++)
#pragma unroll
            for (int q = 0; q < 4; q++) acc[i][j][q] = 0.f;

    for (int chunk = 0; chunk < 6; chunk++) {
        int kt = chunk * 64;
        __syncthreads();
#pragma unroll
        for (int it = 0; it < 4; it++) {
            int idx = tid + it * 256;
            int row = idx >> 3, g = idx & 7;
            size_t go = (size_t)(obase + row) * C_ + kt + g * 8;
            *(uint4*)(Ah + row * SGA + g * 8) = *(const uint4*)(Awh + go);
            *(uint4*)(Al + row * SGA + g * 8) = *(const uint4*)(Awl + go);
        }
#pragma unroll
        for (int it = 0; it < 8; it++) {
            int idx = tid + it * 256;
            int row = idx >> 4, g = idx & 15;
            float4 f = make_float4(0.f, 0.f, 0.f, 0.f);
            if (nbase + row < N_)
                f = *(const float4*)(X + (size_t)(nbase + row) * C_ + kt + g * 4);
            bf16 h0, l0, h1, l1, h2, l2, h3, l3;
            split_bf(f.x, h0, l0); split_bf(f.y, h1, l1);
            split_bf(f.z, h2, l2); split_bf(f.w, h3, l3);
            *(uint2*)(Xh + row * SGA + g * 4) = make_uint2(pk_bf(h0, h1), pk_bf(h2, h3));
            *(uint2*)(Xl + row * SGA + g * 4) = make_uint2(pk_bf(l0, l1), pk_bf(l2, l3));
        }
        __syncthreads();

#pragma unroll
        for (int ks = 0; ks < 4; ks++) {
            int kk = ks * 16;
            uint32_t ah[2][4], al[2][4];
#pragma unroll
            for (int mi = 0; mi < 2; mi++) {
                int r = wm * 32 + mi * 16 + (lane & 15);
                int cofs = kk + ((lane >> 4) << 3);
                uint32_t off = (uint32_t)(r * SGA + cofs) * 2;
                LDSM4(ah[mi], baAh + off);
                LDSM4(al[mi], baAl + off);
            }
#pragma unroll
            for (int ni = 0; ni < 8; ni++) {
                int rn = wn * 64 + ni * 8 + (lane & 7);
                int cofs = kk + (((lane >> 3) & 1) << 3);
                uint32_t off = (uint32_t)(rn * SGA + cofs) * 2;
                uint32_t bh[2], bl[2];
                LDSM2(bh, baXh + off);
                LDSM2(bl, baXl + off);
#pragma unroll
                for (int mi = 0; mi < 2; mi++) {
                    MMA16816(acc[mi][ni], ah[mi], bh);
                    MMA16816(acc[mi][ni], ah[mi], bl);
                    MMA16816(acc[mi][ni], al[mi], bh);
                }
            }
        }
    }
    __syncthreads();

    float* stage = (float*)dyn;
#pragma unroll
    for (int mi = 0; mi < 2; mi++)
#pragma unroll
        for (int ni = 0; ni < 8; ni++) {
            int m = wm * 32 + mi * 16 + (lane >> 2);
            int n = wn * 64 + ni * 8 + ((lane & 3) << 1);
            *(float2*)&stage[ssw(m, n)] = make_float2(acc[mi][ni][0], acc[mi][ni][1]);
            *(float2*)&stage[ssw(m + 8, n)] = make_float2(acc[mi][ni][2], acc[mi][ni][3]);
        }
    __syncthreads();

    if (!TRANS_OUT) {
        float* outp = g_qkv;
        for (int idx = tid; idx < 128 * 32; idx += 256) {
            int m = idx >> 5, nq = (idx & 31) * 4;
            int n0 = nbase + nq;
            if (n0 < N_) {
                float4 v = *(const float4*)&stage[ssw(m, nq)];
                *(float4*)(outp + ((size_t)b * R1 + obase + m) * N_ + n0) = v;
            }
        }
    } else {
        float* outp = g_projo;
        for (int idx = tid; idx < 128 * 32; idx += 256) {
            int n = idx >> 5, mq = (idx & 31) * 4;
            int ng = nbase + n;
            if (ng < N_) {
                int xw = (((mq >> 2) & 7) << 2);
                float4 v;
                v.x = stage[(mq + 0) * 128 + (n ^ xw)] + bias[obase + mq + 0];
                v.y = stage[(mq + 1) * 128 + (n ^ xw)] + bias[obase + mq + 1];
                v.z = stage[(mq + 2) * 128 + (n ^ xw)] + bias[obase + mq + 2];
                v.w = stage[(mq + 3) * 128 + (n ^ xw)] + bias[obase + mq + 3];
                *(float4*)(outp + ((size_t)b * N_ + ng) * C_ + obase + mq) = v;
            }
        }
    }
}

// ------------------------- 5) flash attention: f16x2 exp + f16 PV ----------
#define FQS 56
#define FVS 72
#define FOFF_QH 0
#define FOFF_QL (FOFF_QH + 128 * FQS * 2)
#define FOFF_KH (FOFF_QL + 128 * FQS * 2)
#define FOFF_KL (FOFF_KH + 64 * FQS * 2)
#define FOFF_VH (FOFF_KL + 64 * FQS * 2)
#define FOFF_VL (FOFF_VH + 48 * FVS * 2)
#define FLASH_DSMEM (FOFF_VL + 48 * FVS * 2)

__global__ __launch_bounds__(256, 2) void flash_mma() {
    extern __shared__ __align__(16) char fdyn[];
    bf16*   Qh = (bf16*)(fdyn + FOFF_QH);
    bf16*   Ql = (bf16*)(fdyn + FOFF_QL);
    bf16*   Kh = (bf16*)(fdyn + FOFF_KH);
    bf16*   Kl = (bf16*)(fdyn + FOFF_KL);
    __half* Vh = (__half*)(fdyn + FOFF_VH);
    __half* Vl = (__half*)(fdyn + FOFF_VL);

    int mbase = blockIdx.x * 128, h = blockIdx.y, b = blockIdx.z;
    int tid = threadIdx.x;
    int lane = tid & 31, w = tid >> 5;
    const float* qkb = g_qkv + ((size_t)b * R3C + (size_t)h * (3 * HD)) * N_;

    uint32_t baQh = smem_u32(Qh), baQl = smem_u32(Ql);
    uint32_t baKh = smem_u32(Kh), baKl = smem_u32(Kl);
    uint32_t baVh = smem_u32(Vh), baVl = smem_u32(Vl);

    for (int idx = tid; idx < HD * 128; idx += 256) {
        int d = idx >> 7, m = idx & 127;
        int mg = mbase + m;
        float f = (mg < N_) ? qkb[(size_t)d * N_ + mg] : 0.f;
        bf16 hh, ll;
        split_bf(f, hh, ll);
        Qh[m * FQS + d] = hh;
        Ql[m * FQS + d] = ll;
    }
    __syncthreads();

    uint32_t qh[3][4], ql[3][4];
#pragma unroll
    for (int ks = 0; ks < 3; ks++) {
        int r = w * 16 + (lane & 15);
        int cofs = ks * 16 + ((lane >> 4) << 3);
        uint32_t off = (uint32_t)(r * FQS + cofs) * 2;
        LDSM4(qh[ks], baQh + off);
        LDSM4(ql[ks], baQl + off);
    }

    float mrow[2] = {-1e30f, -1e30f};
    float lrow[2] = {0.f, 0.f};
    float o[6][4];
#pragma unroll
    for (int i = 0; i < 6; i++)
#pragma unroll
        for (int j = 0; j < 4; j++) o[i][j] = 0.f;

    for (int t = 0; t < 13; t++) {
        int kb = t * 64;
        __syncthreads();
        for (int idx = tid; idx < HD * 64; idx += 256) {
            int d = idx >> 6, kk = idx & 63;
            int kg = kb + kk;
            float f = (kg < N_) ? qkb[(size_t)(HD + d) * N_ + kg] : 0.f;
            bf16 hh, ll;
            split_bf(f, hh, ll);
            Kh[kk * FQS + d] = hh;
            Kl[kk * FQS + d] = ll;
        }
        for (int idx = tid; idx < HD * 64; idx += 256) {
            int d = idx >> 6, kk = idx & 63;
            int kg = kb + kk;
            float f = (kg < N_) ? qkb[(size_t)(2 * HD + d) * N_ + kg] : 0.f;
            __half hh, ll;
            split_h(f, hh, ll);
            Vh[d * FVS + kk] = hh;
            Vl[d * FVS + kk] = ll;
        }
        __syncthreads();

        float sacc[8][4];
#pragma unroll
        for (int nb = 0; nb < 8; nb++)
#pragma unroll
            for (int j = 0; j < 4; j++) sacc[nb][j] = 0.f;
#pragma unroll
        for (int ks = 0; ks < 3; ks++) {
#pragma unroll
            for (int nbp = 0; nbp < 4; nbp++) {
                int rn = nbp * 16 + ((lane >> 4) & 1) * 8 + (lane & 7);
                int cofs = ks * 16 + ((lane >> 3) & 1) * 8;
                uint32_t off = (uint32_t)(rn * FQS + cofs) * 2;
                uint32_t kbh[4], kbl[4];
                LDSM4(kbh, baKh + off);
                LDSM4(kbl, baKl + off);
                MMA16816(sacc[2 * nbp], qh[ks], kbh);
                MMA16816(sacc[2 * nbp], qh[ks], kbl);
                MMA16816(sacc[2 * nbp], ql[ks], kbh);
                MMA16816(sacc[2 * nbp + 1], qh[ks], kbh + 2);
                MMA16816(sacc[2 * nbp + 1], qh[ks], kbl + 2);
                MMA16816(sacc[2 * nbp + 1], ql[ks], kbh + 2);
            }
        }

#pragma unroll
        for (int nb = 0; nb < 8; nb++)
#pragma unroll
            for (int j = 0; j < 4; j++) sacc[nb][j] *= ATTN_SCALE;
        if (kb + 64 > N_) {
#pragma unroll
            for (int nb = 0; nb < 8; nb++)
#pragma unroll
                for (int j = 0; j < 4; j++) {
                    int kg = kb + nb * 8 + (lane & 3) * 2 + (j & 1);
                    if (kg >= N_) sacc[nb][j] = -1e30f;
                }
        }

        float mx0 = -1e30f, mx1 = -1e30f;
#pragma unroll
        for (int nb = 0; nb < 8; nb++) {
            mx0 = fmaxf(mx0, fmaxf(sacc[nb][0], sacc[nb][1]));
            mx1 = fmaxf(mx1, fmaxf(sacc[nb][2], sacc[nb][3]));
        }
        mx0 = fmaxf(mx0, __shfl_xor_sync(0xffffffffu, mx0, 1));
        mx0 = fmaxf(mx0, __shfl_xor_sync(0xffffffffu, mx0, 2));
        mx1 = fmaxf(mx1, __shfl_xor_sync(0xffffffffu, mx1, 1));
        mx1 = fmaxf(mx1, __shfl_xor_sync(0xffffffffu, mx1, 2));
        float mn0 = fmaxf(mrow[0], mx0), mn1 = fmaxf(mrow[1], mx1);
        float f0 = __expf(mrow[0] - mn0), f1 = __expf(mrow[1] - mn1);
        mrow[0] = mn0; mrow[1] = mn1;

        float c0 = -mn0 * LOG2E, c1 = -mn1 * LOG2E;
        uint32_t pa[4][4];
        uint32_t sum01 = 0, sum23 = 0;
#pragma unroll
        for (int nb = 0; nb < 8; nb++) {
            float t0 = fmaf(sacc[nb][0], LOG2E, c0);
            float t1 = fmaf(sacc[nb][1], LOG2E, c0);
            float t2 = fmaf(sacc[nb][2], LOG2E, c1);
            float t3 = fmaf(sacc[nb][3], LOG2E, c1);
            uint32_t p01 = ex2_h2(cvt_h2(t0, t1));
            uint32_t p23 = ex2_h2(cvt_h2(t2, t3));
            sum01 = addh2(sum01, p01);
            sum23 = addh2(sum23, p23);
            int ks2 = nb >> 1, ri = (nb & 1) * 2;
            pa[ks2][ri] = p01;
            pa[ks2][ri + 1] = p23;
        }
        float ls0 = h2sum(sum01), ls1 = h2sum(sum23);
        ls0 += __shfl_xor_sync(0xffffffffu, ls0, 1);
        ls0 += __shfl_xor_sync(0xffffffffu, ls0, 2);
        ls1 += __shfl_xor_sync(0xffffffffu, ls1, 1);
        ls1 += __shfl_xor_sync(0xffffffffu, ls1, 2);
        lrow[0] = lrow[0] * f0 + ls0;
        lrow[1] = lrow[1] * f1 + ls1;

#pragma unroll
        for (int db = 0; db < 6; db++) {
            o[db][0] *= f0; o[db][1] *= f0;
            o[db][2] *= f1; o[db][3] *= f1;
        }
#pragma unroll
        for (int ks = 0; ks < 4; ks++) {
#pragma unroll
            for (int dbp = 0; dbp < 3; dbp++) {
                int rn = dbp * 16 + ((lane >> 4) & 1) * 8 + (lane & 7);
                int cofs = ks * 16 + ((lane >> 3) & 1) * 8;
                uint32_t off = (uint32_t)(rn * FVS + cofs) * 2;
                uint32_t vbh[4], vbl[4];
                LDSM4(vbh, baVh + off);
                LDSM4(vbl, baVl + off);
                MMA16816H(o[2 * dbp], pa[ks], vbh);
                MMA16816H(o[2 * dbp], pa[ks], vbl);
                MMA16816H(o[2 * dbp + 1], pa[ks], vbh + 2);
                MMA16816H(o[2 * dbp + 1], pa[ks], vbl + 2);
            }
        }
    }

    __syncthreads();
    float* stage = (float*)fdyn;
    float li0 = 1.f / lrow[0], li1 = 1.f / lrow[1];
    int r = lane >> 2, cq = (lane & 3) * 2;
#pragma unroll
    for (int db = 0; db < 6; db++) {
        int m0 = w * 16 + r;
        *(float2*)&stage[m0 * 52 + db * 8 + cq] = make_float2(o[db][0] * li0, o[db][1] * li0);
        *(float2*)&stage[(m0 + 8) * 52 + db * 8 + cq] = make_float2(o[db][2] * li1, o[db][3] * li1);
    }
    __syncthreads();
    for (int idx = tid; idx < 128 * 12; idx += 256) {
        int m = idx / 12, dq = (idx % 12) * 4;
        int mg = mbase + m;
        if (mg < N_) {
            float4 v = *(const float4*)&stage[m * 52 + dq];
            *(float4*)(g_attno + ((size_t)b * N_ + mg) * C_ + h * HD + dq) = v;
        }
    }
}

// ------------------------- 7) scatter (float4 stores) ----------------------
__global__ void scatter_kernel(float* __restrict__ out) {
    __shared__ __align__(16) float out9[C_ * 10];
    __shared__ float aff_s[64 * 9];
    int n = blockIdx.x, b = blockIdx.y;
    int y = n / HH_, x = n % HH_;
    int tid = threadIdx.x;

#pragma unroll
    for (int k = 0; k < 9; k++) {
        int yy = y + k / 3 - 1, xx = x + k % 3 - 1;
        float v = 0.f;
        if (yy >= 0 && yy < HH_ && xx >= 0 && xx < HH_)
            v = g_projo[((size_t)b * N_ + yy * HH_ + xx) * C_ + tid];
        out9[tid * 10 + k] = v;
    }
    size_t abase = ((size_t)b * N_ + n) * 576;
    for (int idx = tid; idx < 576; idx += 384) aff_s[idx] = g_aff[abase + idx];
    __syncthreads();

    int pg = tid & 15, cg = tid >> 4;
    int py = pg >> 1, px4 = (pg & 1) * 4;
    int p0 = py * 8 + px4;
    ull av2[4][4];
    float av8[4];
#pragma unroll
    for (int i = 0; i < 4; i++) {
        const float* a = &aff_s[(p0 + i) * 9];
        av2[i][0] = pk2(a[0], a[1]);
        av2[i][1] = pk2(a[2], a[3]);
        av2[i][2] = pk2(a[4], a[5]);
        av2[i][3] = pk2(a[6], a[7]);
        av8[i] = a[8];
    }
    float* obase = out + ((size_t)b * C_ * H_ + (size_t)(y * 8 + py)) * H_ + (size_t)x * 8 + px4;
    for (int c = cg; c < C_; c += 24) {
        const float* o9 = &out9[c * 10];
        ull o01 = *(const ull*)(o9 + 0);
        ull o23 = *(const ull*)(o9 + 2);
        ull o45 = *(const ull*)(o9 + 4);
        ull o67 = *(const ull*)(o9 + 6);
        float o8 = o9[8];
        float res[4];
#pragma unroll
        for (int i = 0; i < 4; i++) {
            ull acc2 = 0ull;
            FMA2(acc2, av2[i][0], o01);
            FMA2(acc2, av2[i][1], o23);
            FMA2(acc2, av2[i][2], o45);
            FMA2(acc2, av2[i][3], o67);
            float lo, hi;
            upk2(acc2, lo, hi);
            res[i] = lo + hi + av8[i] * o8;
        }
        *(float4*)(obase + (size_t)c * H_ * H_) = make_float4(res[0], res[1], res[2], res[3]);
    }
}

// ------------------------- launch ------------------------------------------
extern "C" void kernel_launch(void* const* d_in, const int* in_sizes, int n_in,
                              void* d_out, int out_size) {
    const float* xs     = (const float*)d_in[0];
    const float* qkv_w  = (const float*)d_in[2];
    const float* proj_w = (const float*)d_in[3];
    const float* proj_b = (const float*)d_in[4];
    float* out = (float*)d_out;

    cudaFuncSetAttribute(site_kernel, cudaFuncAttributeMaxDynamicSharedMemorySize,
                         SITE_SMEM_FLOATS * (int)sizeof(float));
    cudaFuncSetAttribute(flash_mma, cudaFuncAttributeMaxDynamicSharedMemorySize, FLASH_DSMEM);
    cudaFuncSetAttribute(gemm_mma<false>, cudaFuncAttributeMaxDynamicSharedMemorySize, GEMM_DSMEM);
    cudaFuncSetAttribute(gemm_mma<true>, cudaFuncAttributeMaxDynamicSharedMemorySize, GEMM_DSMEM);

    split_w<<<144, 256>>>(qkv_w, proj_w);
    pool_kernel<<<dim3(HH_, C_, B_), 224>>>(xs);
    site_kernel<<<dim3(N_, B_), 384, SITE_SMEM_FLOATS * sizeof(float)>>>(xs);
    gather_kernel<<<dim3(N_, B_), C_>>>();
    gemm_mma<false><<<dim3(7, 9, B_), 256, GEMM_DSMEM>>>(nullptr, R3C);
    flash_mma<<<dim3(7, HEADS, B_), 256, FLASH_DSMEM>>>();
    gemm_mma<true><<<dim3(7, 3, B_), 256, GEMM_DSMEM>>>(proj_b, C_);
    scatter_kernel<<<dim3(N_, B_), 384>>>(out);
}

// round 16
// speedup vs baseline: 1.0576x; 1.0576x over previous
#include <cuda_runtime.h>
#include <cuda_bf16.h>
#include <cuda_fp16.h>
#include <math.h>
#include <stdint.h>

#define B_    4
#define C_    384
#define H_    224
#define HH_   28
#define N_    784
#define HEADS 8
#define HD    48
#define R3C   (3 * C_)

#define AFF_SCALE  0.05103103630798288f   /* 384^-0.5 */
#define ATTN_SCALE 0.14433756729740643f   /* 48^-0.5 */
#define LOG2E      1.4426950408889634f

typedef unsigned long long ull;
typedef __nv_bfloat16 bf16;

__device__ __forceinline__ ull pk2(float a, float b) {
    ull r;
    asm("mov.b64 %0, {%1, %2};" : "=l"(r) : "f"(a), "f"(b));
    return r;
}
__device__ __forceinline__ void upk2(ull v, float& a, float& b) {
    asm("mov.b64 {%0, %1}, %2;" : "=f"(a), "=f"(b) : "l"(v));
}
#define FMA2(d, a, b) asm("fma.rn.f32x2 %0, %1, %2, %0;" : "+l"(d) : "l"(a), "l"(b))

__device__ __forceinline__ uint32_t smem_u32(const void* p) {
    uint32_t a;
    asm("{ .reg .u64 t; cvta.to.shared.u64 t, %1; cvt.u32.u64 %0, t; }" : "=r"(a) : "l"(p));
    return a;
}
__device__ __forceinline__ uint32_t pk_bf(bf16 a, bf16 b) {
    uint16_t ra = *(uint16_t*)&a, rb = *(uint16_t*)&b;
    return (uint32_t)ra | ((uint32_t)rb << 16);
}
__device__ __forceinline__ void split_bf(float f, bf16& h, bf16& l) {
    h = __float2bfloat16_rn(f);
    l = __float2bfloat16_rn(f - __bfloat162float(h));
}
__device__ __forceinline__ void split_h(float f, __half& h, __half& l) {
    h = __float2half_rn(f);
    l = __float2half_rn(f - __half2float(h));
}
__device__ __forceinline__ uint32_t cvt_h2(float a, float b) {
    uint32_t r;
    asm("cvt.rn.f16x2.f32 %0, %1, %2;" : "=r"(r) : "f"(b), "f"(a));
    return r;
}
__device__ __forceinline__ uint32_t ex2_h2(uint32_t x) {
    uint32_t r;
    asm("ex2.approx.f16x2 %0, %1;" : "=r"(r) : "r"(x));
    return r;
}
__device__ __forceinline__ uint32_t addh2(uint32_t a, uint32_t b) {
    uint32_t r;
    asm("add.f16x2 %0, %1, %2;" : "=r"(r) : "r"(a), "r"(b));
    return r;
}
__device__ __forceinline__ float h2sum(uint32_t v) {
    __half2 h = *(__half2*)&v;
    return __low2float(h) + __high2float(h);
}

#define LDSM4(r, addr) \
    asm volatile("ldmatrix.sync.aligned.m8n8.x4.shared.b16 {%0,%1,%2,%3}, [%4];" \
                 : "=r"((r)[0]), "=r"((r)[1]), "=r"((r)[2]), "=r"((r)[3]) : "r"(addr))
#define LDSM2(r, addr) \
    asm volatile("ldmatrix.sync.aligned.m8n8.x2.shared.b16 {%0,%1}, [%2];" \
                 : "=r"((r)[0]), "=r"((r)[1]) : "r"(addr))
#define MMA16816(d, a, b) \
    asm volatile("mma.sync.aligned.m16n8k16.row.col.f32.bf16.bf16.f32 " \
                 "{%0,%1,%2,%3}, {%4,%5,%6,%7}, {%8,%9}, {%0,%1,%2,%3};" \
                 : "+f"((d)[0]), "+f"((d)[1]), "+f"((d)[2]), "+f"((d)[3]) \
                 : "r"((a)[0]), "r"((a)[1]), "r"((a)[2]), "r"((a)[3]), \
                   "r"((b)[0]), "r"((b)[1]))
#define MMA16816H(d, a, b) \
    asm volatile("mma.sync.aligned.m16n8k16.row.col.f32.f16.f16.f32 " \
                 "{%0,%1,%2,%3}, {%4,%5,%6,%7}, {%8,%9}, {%0,%1,%2,%3};" \
                 : "+f"((d)[0]), "+f"((d)[1]), "+f"((d)[2]), "+f"((d)[3]) \
                 : "r"((a)[0]), "r"((a)[1]), "r"((a)[2]), "r"((a)[3]), \
                   "r"((b)[0]), "r"((b)[1]))

__device__ __forceinline__ void cpa16(uint32_t saddr, const void* g) {
    asm volatile("cp.async.cg.shared.global [%0], [%1], 16;" :: "r"(saddr), "l"(g));
}
#define CPA_COMMIT() asm volatile("cp.async.commit_group;" ::: "memory")
#define CPA_WAIT(n)  asm volatile("cp.async.wait_group %0;" :: "n"(n) : "memory")

// ------------------------- scratch (device globals, no allocs) -------------
__device__ float g_sf[B_ * N_ * C_];
__device__ float g_aff[B_ * N_ * 64 * 9];
__device__ float g_affsum[B_ * N_ * 9];
__device__ float g_sft_site[B_ * N_ * 9 * C_];
__device__ float g_sftn[B_ * N_ * C_];
__device__ float g_qkv[B_ * R3C * N_];
__device__ float g_attno[B_ * N_ * C_];
__device__ float g_projo[B_ * N_ * C_];
__device__ bf16 g_qkvw_h[R3C * C_], g_qkvw_l[R3C * C_];
__device__ bf16 g_projw_h[C_ * C_], g_projw_l[C_ * C_];

// ------------------------- 0) split weights --------------------------------
__global__ void split_w(const float* __restrict__ qkv_w, const float* __restrict__ proj_w) {
    int idx = blockIdx.x * 256 + threadIdx.x;
    for (int i = idx; i < R3C * C_; i += gridDim.x * 256) {
        bf16 h, l;
        split_bf(qkv_w[i], h, l);
        g_qkvw_h[i] = h;
        g_qkvw_l[i] = l;
    }
    for (int i = idx; i < C_ * C_; i += gridDim.x * 256) {
        bf16 h, l;
        split_bf(proj_w[i], h, l);
        g_projw_h[i] = h;
        g_projw_l[i] = l;
    }
}

// ------------------------- 1) 8x8 average pool (float4) --------------------
__global__ void pool_kernel(const float* __restrict__ xs) {
    int y = blockIdx.x, c = blockIdx.y, b = blockIdx.z;
    int t = threadIdx.x;
    int r = t / 28, xx = t - r * 28;
    const float* base = xs + ((size_t)(b * C_ + c) * H_ + (size_t)y * 8) * H_;
    float4 a = *(const float4*)(base + (size_t)r * H_ + xx * 8);
    float4 d = *(const float4*)(base + (size_t)r * H_ + xx * 8 + 4);
    float partial = (a.x + a.y) + (a.z + a.w) + (d.x + d.y) + (d.z + d.w);
    __shared__ float sm[224];
    sm[r * 28 + xx] = partial;
    __syncthreads();
    if (t < HH_) {
        float acc = 0.f;
#pragma unroll
        for (int i = 0; i < 8; i++) acc += sm[i * 28 + t];
        g_sf[((size_t)b * N_ + (size_t)y * HH_ + t) * C_ + c] = acc * (1.0f / 64.0f);
    }
}

// ------------------------- 2) site kernel v6: pixel-pair phase A -----------
#define CK 96
#define PIXPAD 68
#define BUF_F (CK * PIXPAD)              /* 6528 */
#define S_SF9  (4 * BUF_F)               /* 26112 */
#define S_STG  (S_SF9 + C_ * 10)         /* 29952 */
#define S_AFF  (S_STG + 6912)            /* 36864 */
#define SITE_SMEM_FLOATS (S_AFF + 640)   /* 37504 floats = 150016 B */

__global__ __launch_bounds__(384, 1) void site_kernel(const float* __restrict__ xs) {
    extern __shared__ __align__(16) float sm[];
    float* sf9   = sm + S_SF9;
    float* stg   = sm + S_STG;
    float* aff_s = sm + S_AFF;

    int n = blockIdx.x, b = blockIdx.y;
    int y = n / HH_, x = n % HH_;
    int tid = threadIdx.x;
    const float* xbase = xs + ((size_t)b * C_ * H_ + (size_t)y * 8) * H_ + (size_t)x * 8;

    // issue chunk 0
    for (int i = tid; i < CK * 16; i += 384) {
        int cl = i >> 4, r = i & 15;
        int py = r >> 1, px4 = (r & 1) << 2;
        cpa16(smem_u32(&sm[cl * PIXPAD + py * 8 + px4]),
              xbase + ((size_t)cl * H_ + py) * H_ + px4);
    }
    CPA_COMMIT();

#pragma unroll
    for (int k = 0; k < 9; k++) {
        int yy = y + k / 3 - 1, xx = x + k % 3 - 1;
        float v = 0.f;
        if (yy >= 0 && yy < HH_ && xx >= 0 && xx < HH_)
            v = g_sf[((size_t)b * N_ + yy * HH_ + xx) * C_ + tid];
        sf9[tid * 10 + k] = v;
    }

    // phase A: thread = (pixel pair 0..31) x (csub 0..11, 8 channels each)
    int ppair = tid & 31, csub = tid >> 5;
    int p0 = ppair * 2;
    ull lacc[2][4];
    float lacc8[2];
#pragma unroll
    for (int i = 0; i < 2; i++) {
        lacc8[i] = 0.f;
#pragma unroll
        for (int q = 0; q < 4; q++) lacc[i][q] = 0ull;
    }
    for (int ck = 0; ck < 4; ck++) {
        if (ck < 3) {
            float* nb = sm + (ck + 1) * BUF_F;
            int cbase = (ck + 1) * CK;
            for (int i = tid; i < CK * 16; i += 384) {
                int cl = i >> 4, r = i & 15;
                int py = r >> 1, px4 = (r & 1) << 2;
                cpa16(smem_u32(&nb[cl * PIXPAD + py * 8 + px4]),
                      xbase + ((size_t)(cbase + cl) * H_ + py) * H_ + px4);
            }
            CPA_COMMIT();
            CPA_WAIT(1);
        } else {
            CPA_WAIT(0);
        }
        __syncthreads();
        const float* buf = sm + ck * BUF_F;
#pragma unroll
        for (int cc = 0; cc < 8; cc++) {
            int cl = csub * 8 + cc;
            float2 pv2 = *(const float2*)&buf[cl * PIXPAD + p0];
            float pv[2] = {pv2.x, pv2.y};
            const float* s9 = &sf9[(ck * CK + cl) * 10];
            ull s01 = *(const ull*)(s9 + 0);
            ull s23 = *(const ull*)(s9 + 2);
            ull s45 = *(const ull*)(s9 + 4);
            ull s67 = *(const ull*)(s9 + 6);
            float s8 = s9[8];
#pragma unroll
            for (int i = 0; i < 2; i++) {
                ull pp = pk2(pv[i], pv[i]);
                FMA2(lacc[i][0], pp, s01);
                FMA2(lacc[i][1], pp, s23);
                FMA2(lacc[i][2], pp, s45);
                FMA2(lacc[i][3], pp, s67);
                lacc8[i] = fmaf(pv[i], s8, lacc8[i]);
            }
        }
    }
#pragma unroll
    for (int i = 0; i < 2; i++) {
        float l[9];
        upk2(lacc[i][0], l[0], l[1]);
        upk2(lacc[i][1], l[2], l[3]);
        upk2(lacc[i][2], l[4], l[5]);
        upk2(lacc[i][3], l[6], l[7]);
        l[8] = lacc8[i];
#pragma unroll
        for (int k = 0; k < 9; k++) stg[csub * 576 + (p0 + i) * 9 + k] = l[k];
    }
    __syncthreads();
    for (int idx = tid; idx < 576; idx += 384) {
        float s = 0.f;
#pragma unroll
        for (int ch = 0; ch < 12; ch++) s += stg[ch * 576 + idx];
        int pp = idx / 9, k = idx - pp * 9;
        aff_s[pp * 10 + k] = s * AFF_SCALE;
    }
    __syncthreads();
    if (tid < 64) {
        float m = -1e30f;
#pragma unroll
        for (int k = 0; k < 9; k++) m = fmaxf(m, aff_s[tid * 10 + k]);
        float e[9], ssum = 0.f;
#pragma unroll
        for (int k = 0; k < 9; k++) { e[k] = __expf(aff_s[tid * 10 + k] - m); ssum += e[k]; }
        float inv = 1.f / ssum;
#pragma unroll
        for (int k = 0; k < 9; k++) aff_s[tid * 10 + k] = e[k] * inv;
    }
    __syncthreads();
    size_t abase = ((size_t)b * N_ + n) * 576;
    for (int idx = tid; idx < 576; idx += 384) {
        int pp = idx / 9, k = idx - pp * 9;
        g_aff[abase + idx] = aff_s[pp * 10 + k];
    }
    if (tid < 9) {
        float s = 0.f;
        for (int pp = 0; pp < 64; pp++) s += aff_s[pp * 10 + tid];
        g_affsum[((size_t)b * N_ + n) * 9 + tid] = s;
    }

    // phase B: unchanged from R14
    int cl_t = tid % 96, psub = tid / 96;
    size_t sbase = ((size_t)b * N_ + n) * 9;
    for (int ck = 0; ck < 4; ck++) {
        const float* buf = sm + ck * BUF_F;
        ull a2[4] = {0, 0, 0, 0};
        float a8 = 0.f;
#pragma unroll
        for (int p4 = 0; p4 < 4; p4++) {
            int pp = psub * 16 + p4 * 4;
            float4 pv4 = *(const float4*)&buf[cl_t * PIXPAD + pp];
            float pv[4] = {pv4.x, pv4.y, pv4.z, pv4.w};
#pragma unroll
            for (int pi = 0; pi < 4; pi++) {
                ull pd = pk2(pv[pi], pv[pi]);
                const float* a9 = &aff_s[(pp + pi) * 10];
                FMA2(a2[0], pd, *(const ull*)(a9 + 0));
                FMA2(a2[1], pd, *(const ull*)(a9 + 2));
                FMA2(a2[2], pd, *(const ull*)(a9 + 4));
                FMA2(a2[3], pd, *(const ull*)(a9 + 6));
                a8 = fmaf(pv[pi], a9[8], a8);
            }
        }
        __syncthreads();
        {
            float r[9];
            upk2(a2[0], r[0], r[1]);
            upk2(a2[1], r[2], r[3]);
            upk2(a2[2], r[4], r[5]);
            upk2(a2[3], r[6], r[7]);
            r[8] = a8;
#pragma unroll
            for (int k = 0; k < 9; k++) stg[psub * 864 + k * 96 + cl_t] = r[k];
        }
        __syncthreads();
        for (int idx = tid; idx < 864; idx += 384) {
            float s = stg[idx] + stg[864 + idx] + stg[1728 + idx] + stg[2592 + idx];
            int k = idx / 96, cl = idx - k * 96;
            g_sft_site[(sbase + k) * C_ + ck * CK + cl] = s;
        }
        __syncthreads();
    }
}

// ------------------------- 3) fold3 gather + normalize ---------------------
__global__ void gather_kernel() {
    int n = blockIdx.x, b = blockIdx.y;
    int y = n / HH_, x = n % HH_;
    int c = threadIdx.x;
    float acc = 0.f, asum = 0.f;
#pragma unroll
    for (int k = 0; k < 9; k++) {
        int i = k / 3, j = k % 3;
        int sy = y + 1 - i, sx = x + 1 - j;
        if (sy >= 0 && sy < HH_ && sx >= 0 && sx < HH_) {
            size_t sb = ((size_t)b * N_ + sy * HH_ + sx) * 9 + k;
            acc += g_sft_site[sb * C_ + c];
            asum += g_affsum[sb];
        }
    }
    g_sftn[((size_t)b * N_ + n) * C_ + c] = acc / (asum + 1e-12f);
}

// ------------------------- 4/6) mma.sync GEMM (pre-split weights) ----------
#define SGA 72
#define GEMM_DSMEM (4 * 128 * SGA * 2)
__device__ __forceinline__ int ssw(int m, int n) { return m * 128 + (n ^ (((m >> 2) & 7) << 2)); }

template <bool TRANS_OUT>
__global__ __launch_bounds__(256, 2) void gemm_mma(const float* __restrict__ bias, int R1) {
    extern __shared__ __align__(16) char dyn[];
    bf16* Ah = (bf16*)dyn;
    bf16* Al = Ah + 128 * SGA;
    bf16* Xh = Al + 128 * SGA;
    bf16* Xl = Xh + 128 * SGA;

    int b = blockIdx.z;
    int obase = blockIdx.y * 128;
    int nbase = blockIdx.x * 128;
    int tid = threadIdx.x;
    int lane = tid & 31, w = tid >> 5;
    int wm = w & 3, wn = w >> 2;
    const bf16* Awh = TRANS_OUT ? g_projw_h : g_qkvw_h;
    const bf16* Awl = TRANS_OUT ? g_projw_l : g_qkvw_l;
    const float* X = (TRANS_OUT ? g_attno : g_sftn) + (size_t)b * N_ * C_;

    uint32_t baAh = smem_u32(Ah), baAl = smem_u32(Al);
    uint32_t baXh = smem_u32(Xh), baXl = smem_u32(Xl);

    float acc[2][8][4];
#pragma unroll
    for (int i = 0; i < 2; i++)
#pragma unroll
        for (int j = 0; j < 8; j++)
#pragma unroll
            for (int q = 0; q < 4; q++) acc[i][j][q] = 0.f;

    for (int chunk = 0; chunk < 6; chunk++) {
        int kt = chunk * 64;
        __syncthreads();
#pragma unroll
        for (int it = 0; it < 4; it++) {
            int idx = tid + it * 256;
            int row = idx >> 3, g = idx & 7;
            size_t go = (size_t)(obase + row) * C_ + kt + g * 8;
            *(uint4*)(Ah + row * SGA + g * 8) = *(const uint4*)(Awh + go);
            *(uint4*)(Al + row * SGA + g * 8) = *(const uint4*)(Awl + go);
        }
#pragma unroll
        for (int it = 0; it < 8; it++) {
            int idx = tid + it * 256;
            int row = idx >> 4, g = idx & 15;
            float4 f = make_float4(0.f, 0.f, 0.f, 0.f);
            if (nbase + row < N_)
                f = *(const float4*)(X + (size_t)(nbase + row) * C_ + kt + g * 4);
            bf16 h0, l0, h1, l1, h2, l2, h3, l3;
            split_bf(f.x, h0, l0); split_bf(f.y, h1, l1);
            split_bf(f.z, h2, l2); split_bf(f.w, h3, l3);
            *(uint2*)(Xh + row * SGA + g * 4) = make_uint2(pk_bf(h0, h1), pk_bf(h2, h3));
            *(uint2*)(Xl + row * SGA + g * 4) = make_uint2(pk_bf(l0, l1), pk_bf(l2, l3));
        }
        __syncthreads();

#pragma unroll
        for (int ks = 0; ks < 4; ks++) {
            int kk = ks * 16;
            uint32_t ah[2][4], al[2][4];
#pragma unroll
            for (int mi = 0; mi < 2; mi++) {
                int r = wm * 32 + mi * 16 + (lane & 15);
                int cofs = kk + ((lane >> 4) << 3);
                uint32_t off = (uint32_t)(r * SGA + cofs) * 2;
                LDSM4(ah[mi], baAh + off);
                LDSM4(al[mi], baAl + off);
            }
#pragma unroll
            for (int ni = 0; ni < 8; ni++) {
                int rn = wn * 64 + ni * 8 + (lane & 7);
                int cofs = kk + (((lane >> 3) & 1) << 3);
                uint32_t off = (uint32_t)(rn * SGA + cofs) * 2;
                uint32_t bh[2], bl[2];
                LDSM2(bh, baXh + off);
                LDSM2(bl, baXl + off);
#pragma unroll
                for (int mi = 0; mi < 2; mi++) {
                    MMA16816(acc[mi][ni], ah[mi], bh);
                    MMA16816(acc[mi][ni], ah[mi], bl);
                    MMA16816(acc[mi][ni], al[mi], bh);
                }
            }
        }
    }
    __syncthreads();

    float* stage = (float*)dyn;
#pragma unroll
    for (int mi = 0; mi < 2; mi++)
#pragma unroll
        for (int ni = 0; ni < 8; ni++) {
            int m = wm * 32 + mi * 16 + (lane >> 2);
            int n = wn * 64 + ni * 8 + ((lane & 3) << 1);
            *(float2*)&stage[ssw(m, n)] = make_float2(acc[mi][ni][0], acc[mi][ni][1]);
            *(float2*)&stage[ssw(m + 8, n)] = make_float2(acc[mi][ni][2], acc[mi][ni][3]);
        }
    __syncthreads();

    if (!TRANS_OUT) {
        float* outp = g_qkv;
        for (int idx = tid; idx < 128 * 32; idx += 256) {
            int m = idx >> 5, nq = (idx & 31) * 4;
            int n0 = nbase + nq;
            if (n0 < N_) {
                float4 v = *(const float4*)&stage[ssw(m, nq)];
                *(float4*)(outp + ((size_t)b * R1 + obase + m) * N_ + n0) = v;
            }
        }
    } else {
        float* outp = g_projo;
        for (int idx = tid; idx < 128 * 32; idx += 256) {
            int n = idx >> 5, mq = (idx & 31) * 4;
            int ng = nbase + n;
            if (ng < N_) {
                int xw = (((mq >> 2) & 7) << 2);
                float4 v;
                v.x = stage[(mq + 0) * 128 + (n ^ xw)] + bias[obase + mq + 0];
                v.y = stage[(mq + 1) * 128 + (n ^ xw)] + bias[obase + mq + 1];
                v.z = stage[(mq + 2) * 128 + (n ^ xw)] + bias[obase + mq + 2];
                v.w = stage[(mq + 3) * 128 + (n ^ xw)] + bias[obase + mq + 3];
                *(float4*)(outp + ((size_t)b * N_ + ng) * C_ + obase + mq) = v;
            }
        }
    }
}

// ------------------------- 5) flash attention: f16x2 exp + f16 PV ----------
#define FQS 56
#define FVS 72
#define FOFF_QH 0
#define FOFF_QL (FOFF_QH + 128 * FQS * 2)
#define FOFF_KH (FOFF_QL + 128 * FQS * 2)
#define FOFF_KL (FOFF_KH + 64 * FQS * 2)
#define FOFF_VH (FOFF_KL + 64 * FQS * 2)
#define FOFF_VL (FOFF_VH + 48 * FVS * 2)
#define FLASH_DSMEM (FOFF_VL + 48 * FVS * 2)

__global__ __launch_bounds__(256, 2) void flash_mma() {
    extern __shared__ __align__(16) char fdyn[];
    bf16*   Qh = (bf16*)(fdyn + FOFF_QH);
    bf16*   Ql = (bf16*)(fdyn + FOFF_QL);
    bf16*   Kh = (bf16*)(fdyn + FOFF_KH);
    bf16*   Kl = (bf16*)(fdyn + FOFF_KL);
    __half* Vh = (__half*)(fdyn + FOFF_VH);
    __half* Vl = (__half*)(fdyn + FOFF_VL);

    int mbase = blockIdx.x * 128, h = blockIdx.y, b = blockIdx.z;
    int tid = threadIdx.x;
    int lane = tid & 31, w = tid >> 5;
    const float* qkb = g_qkv + ((size_t)b * R3C + (size_t)h * (3 * HD)) * N_;

    uint32_t baQh = smem_u32(Qh), baQl = smem_u32(Ql);
    uint32_t baKh = smem_u32(Kh), baKl = smem_u32(Kl);
    uint32_t baVh = smem_u32(Vh), baVl = smem_u32(Vl);

    for (int idx = tid; idx < HD * 128; idx += 256) {
        int d = idx >> 7, m = idx & 127;
        int mg = mbase + m;
        float f = (mg < N_) ? qkb[(size_t)d * N_ + mg] : 0.f;
        bf16 hh, ll;
        split_bf(f, hh, ll);
        Qh[m * FQS + d] = hh;
        Ql[m * FQS + d] = ll;
    }
    __syncthreads();

    uint32_t qh[3][4], ql[3][4];
#pragma unroll
    for (int ks = 0; ks < 3; ks++) {
        int r = w * 16 + (lane & 15);
        int cofs = ks * 16 + ((lane >> 4) << 3);
        uint32_t off = (uint32_t)(r * FQS + cofs) * 2;
        LDSM4(qh[ks], baQh + off);
        LDSM4(ql[ks], baQl + off);
    }

    float mrow[2] = {-1e30f, -1e30f};
    float lrow[2] = {0.f, 0.f};
    float o[6][4];
#pragma unroll
    for (int i = 0; i < 6; i++)
#pragma unroll
        for (int j = 0; j < 4; j++) o[i][j] = 0.f;

    for (int t = 0; t < 13; t++) {
        int kb = t * 64;
        __syncthreads();
        for (int idx = tid; idx < HD * 64; idx += 256) {
            int d = idx >> 6, kk = idx & 63;
            int kg = kb + kk;
            float f = (kg < N_) ? qkb[(size_t)(HD + d) * N_ + kg] : 0.f;
            bf16 hh, ll;
            split_bf(f, hh, ll);
            Kh[kk * FQS + d] = hh;
            Kl[kk * FQS + d] = ll;
        }
        for (int idx = tid; idx < HD * 64; idx += 256) {
            int d = idx >> 6, kk = idx & 63;
            int kg = kb + kk;
            float f = (kg < N_) ? qkb[(size_t)(2 * HD + d) * N_ + kg] : 0.f;
            __half hh, ll;
            split_h(f, hh, ll);
            Vh[d * FVS + kk] = hh;
            Vl[d * FVS + kk] = ll;
        }
        __syncthreads();

        float sacc[8][4];
#pragma unroll
        for (int nb = 0; nb < 8; nb++)
#pragma unroll
            for (int j = 0; j < 4; j++) sacc[nb][j] = 0.f;
#pragma unroll
        for (int ks = 0; ks < 3; ks++) {
#pragma unroll
            for (int nbp = 0; nbp < 4; nbp++) {
                int rn = nbp * 16 + ((lane >> 4) & 1) * 8 + (lane & 7);
                int cofs = ks * 16 + ((lane >> 3) & 1) * 8;
                uint32_t off = (uint32_t)(rn * FQS + cofs) * 2;
                uint32_t kbh[4], kbl[4];
                LDSM4(kbh, baKh + off);
                LDSM4(kbl, baKl + off);
                MMA16816(sacc[2 * nbp], qh[ks], kbh);
                MMA16816(sacc[2 * nbp], qh[ks], kbl);
                MMA16816(sacc[2 * nbp], ql[ks], kbh);
                MMA16816(sacc[2 * nbp + 1], qh[ks], kbh + 2);
                MMA16816(sacc[2 * nbp + 1], qh[ks], kbl + 2);
                MMA16816(sacc[2 * nbp + 1], ql[ks], kbh + 2);
            }
        }

#pragma unroll
        for (int nb = 0; nb < 8; nb++)
#pragma unroll
            for (int j = 0; j < 4; j++) sacc[nb][j] *= ATTN_SCALE;
        if (kb + 64 > N_) {
#pragma unroll
            for (int nb = 0; nb < 8; nb++)
#pragma unroll
                for (int j = 0; j < 4; j++) {
                    int kg = kb + nb * 8 + (lane & 3) * 2 + (j & 1);
                    if (kg >= N_) sacc[nb][j] = -1e30f;
                }
        }

        float mx0 = -1e30f, mx1 = -1e30f;
#pragma unroll
        for (int nb = 0; nb < 8; nb++) {
            mx0 = fmaxf(mx0, fmaxf(sacc[nb][0], sacc[nb][1]));
            mx1 = fmaxf(mx1, fmaxf(sacc[nb][2], sacc[nb][3]));
        }
        mx0 = fmaxf(mx0, __shfl_xor_sync(0xffffffffu, mx0, 1));
        mx0 = fmaxf(mx0, __shfl_xor_sync(0xffffffffu, mx0, 2));
        mx1 = fmaxf(mx1, __shfl_xor_sync(0xffffffffu, mx1, 1));
        mx1 = fmaxf(mx1, __shfl_xor_sync(0xffffffffu, mx1, 2));
        float mn0 = fmaxf(mrow[0], mx0), mn1 = fmaxf(mrow[1], mx1);
        float f0 = __expf(mrow[0] - mn0), f1 = __expf(mrow[1] - mn1);
        mrow[0] = mn0; mrow[1] = mn1;

        float c0 = -mn0 * LOG2E, c1 = -mn1 * LOG2E;
        uint32_t pa[4][4];
        uint32_t sum01 = 0, sum23 = 0;
#pragma unroll
        for (int nb = 0; nb < 8; nb++) {
            float t0 = fmaf(sacc[nb][0], LOG2E, c0);
            float t1 = fmaf(sacc[nb][1], LOG2E, c0);
            float t2 = fmaf(sacc[nb][2], LOG2E, c1);
            float t3 = fmaf(sacc[nb][3], LOG2E, c1);
            uint32_t p01 = ex2_h2(cvt_h2(t0, t1));
            uint32_t p23 = ex2_h2(cvt_h2(t2, t3));
            sum01 = addh2(sum01, p01);
            sum23 = addh2(sum23, p23);
            int ks2 = nb >> 1, ri = (nb & 1) * 2;
            pa[ks2][ri] = p01;
            pa[ks2][ri + 1] = p23;
        }
        float ls0 = h2sum(sum01), ls1 = h2sum(sum23);
        ls0 += __shfl_xor_sync(0xffffffffu, ls0, 1);
        ls0 += __shfl_xor_sync(0xffffffffu, ls0, 2);
        ls1 += __shfl_xor_sync(0xffffffffu, ls1, 1);
        ls1 += __shfl_xor_sync(0xffffffffu, ls1, 2);
        lrow[0] = lrow[0] * f0 + ls0;
        lrow[1] = lrow[1] * f1 + ls1;

#pragma unroll
        for (int db = 0; db < 6; db++) {
            o[db][0] *= f0; o[db][1] *= f0;
            o[db][2] *= f1; o[db][3] *= f1;
        }
#pragma unroll
        for (int ks = 0; ks < 4; ks++) {
#pragma unroll
            for (int dbp = 0; dbp < 3; dbp++) {
                int rn = dbp * 16 + ((lane >> 4) & 1) * 8 + (lane & 7);
                int cofs = ks * 16 + ((lane >> 3) & 1) * 8;
                uint32_t off = (uint32_t)(rn * FVS + cofs) * 2;
                uint32_t vbh[4], vbl[4];
                LDSM4(vbh, baVh + off);
                LDSM4(vbl, baVl + off);
                MMA16816H(o[2 * dbp], pa[ks], vbh);
                MMA16816H(o[2 * dbp], pa[ks], vbl);
                MMA16816H(o[2 * dbp + 1], pa[ks], vbh + 2);
                MMA16816H(o[2 * dbp + 1], pa[ks], vbl + 2);
            }
        }
    }

    __syncthreads();
    float* stage = (float*)fdyn;
    float li0 = 1.f / lrow[0], li1 = 1.f / lrow[1];
    int r = lane >> 2, cq = (lane & 3) * 2;
#pragma unroll
    for (int db = 0; db < 6; db++) {
        int m0 = w * 16 + r;
        *(float2*)&stage[m0 * 52 + db * 8 + cq] = make_float2(o[db][0] * li0, o[db][1] * li0);
        *(float2*)&stage[(m0 + 8) * 52 + db * 8 + cq] = make_float2(o[db][2] * li1, o[db][3] * li1);
    }
    __syncthreads();
    for (int idx = tid; idx < 128 * 12; idx += 256) {
        int m = idx / 12, dq = (idx % 12) * 4;
        int mg = mbase + m;
        if (mg < N_) {
            float4 v = *(const float4*)&stage[m * 52 + dq];
            *(float4*)(g_attno + ((size_t)b * N_ + mg) * C_ + h * HD + dq) = v;
        }
    }
}

// ------------------------- 7) scatter (float4 stores) ----------------------
__global__ void scatter_kernel(float* __restrict__ out) {
    __shared__ __align__(16) float out9[C_ * 10];
    __shared__ float aff_s[64 * 9];
    int n = blockIdx.x, b = blockIdx.y;
    int y = n / HH_, x = n % HH_;
    int tid = threadIdx.x;

#pragma unroll
    for (int k = 0; k < 9; k++) {
        int yy = y + k / 3 - 1, xx = x + k % 3 - 1;
        float v = 0.f;
        if (yy >= 0 && yy < HH_ && xx >= 0 && xx < HH_)
            v = g_projo[((size_t)b * N_ + yy * HH_ + xx) * C_ + tid];
        out9[tid * 10 + k] = v;
    }
    size_t abase = ((size_t)b * N_ + n) * 576;
    for (int idx = tid; idx < 576; idx += 384) aff_s[idx] = g_aff[abase + idx];
    __syncthreads();

    int pg = tid & 15, cg = tid >> 4;
    int py = pg >> 1, px4 = (pg & 1) * 4;
    int p0 = py * 8 + px4;
    ull av2[4][4];
    float av8[4];
#pragma unroll
    for (int i = 0; i < 4; i++) {
        const float* a = &aff_s[(p0 + i) * 9];
        av2[i][0] = pk2(a[0], a[1]);
        av2[i][1] = pk2(a[2], a[3]);
        av2[i][2] = pk2(a[4], a[5]);
        av2[i][3] = pk2(a[6], a[7]);
        av8[i] = a[8];
    }
    float* obase = out + ((size_t)b * C_ * H_ + (size_t)(y * 8 + py)) * H_ + (size_t)x * 8 + px4;
    for (int c = cg; c < C_; c += 24) {
        const float* o9 = &out9[c * 10];
        ull o01 = *(const ull*)(o9 + 0);
        ull o23 = *(const ull*)(o9 + 2);
        ull o45 = *(const ull*)(o9 + 4);
        ull o67 = *(const ull*)(o9 + 6);
        float o8 = o9[8];
        float res[4];
#pragma unroll
        for (int i = 0; i < 4; i++) {
            ull acc2 = 0ull;
            FMA2(acc2, av2[i][0], o01);
            FMA2(acc2, av2[i][1], o23);
            FMA2(acc2, av2[i][2], o45);
            FMA2(acc2, av2[i][3], o67);
            float lo, hi;
            upk2(acc2, lo, hi);
            res[i] = lo + hi + av8[i] * o8;
        }
        *(float4*)(obase + (size_t)c * H_ * H_) = make_float4(res[0], res[1], res[2], res[3]);
    }
}

// ------------------------- launch ------------------------------------------
extern "C" void kernel_launch(void* const* d_in, const int* in_sizes, int n_in,
                              void* d_out, int out_size) {
    const float* xs     = (const float*)d_in[0];
    const float* qkv_w  = (const float*)d_in[2];
    const float* proj_w = (const float*)d_in[3];
    const float* proj_b = (const float*)d_in[4];
    float* out = (float*)d_out;

    cudaFuncSetAttribute(site_kernel, cudaFuncAttributeMaxDynamicSharedMemorySize,
                         SITE_SMEM_FLOATS * (int)sizeof(float));
    cudaFuncSetAttribute(flash_mma, cudaFuncAttributeMaxDynamicSharedMemorySize, FLASH_DSMEM);
    cudaFuncSetAttribute(gemm_mma<false>, cudaFuncAttributeMaxDynamicSharedMemorySize, GEMM_DSMEM);
    cudaFuncSetAttribute(gemm_mma<true>, cudaFuncAttributeMaxDynamicSharedMemorySize, GEMM_DSMEM);

    split_w<<<144, 256>>>(qkv_w, proj_w);
    pool_kernel<<<dim3(HH_, C_, B_), 224>>>(xs);
    site_kernel<<<dim3(N_, B_), 384, SITE_SMEM_FLOATS * sizeof(float)>>>(xs);
    gather_kernel<<<dim3(N_, B_), C_>>>();
    gemm_mma<false><<<dim3(7, 9, B_), 256, GEMM_DSMEM>>>(nullptr, R3C);
    flash_mma<<<dim3(7, HEADS, B_), 256, FLASH_DSMEM>>>();
    gemm_mma<true><<<dim3(7, 3, B_), 256, GEMM_DSMEM>>>(proj_b, C_);
    scatter_kernel<<<dim3(N_, B_), 384>>>(out);
}

// round 17
// speedup vs baseline: 1.0672x; 1.0091x over previous
#include <cuda_runtime.h>
#include <cuda_bf16.h>
#include <cuda_fp16.h>
#include <math.h>
#include <stdint.h>

#define B_    4
#define C_    384
#define H_    224
#define HH_   28
#define N_    784
#define HEADS 8
#define HD    48
#define R3C   (3 * C_)

#define AFF_SCALE  0.05103103630798288f   /* 384^-0.5 */
#define ATTN_SCALE 0.14433756729740643f   /* 48^-0.5 */
#define LOG2E      1.4426950408889634f

typedef unsigned long long ull;
typedef __nv_bfloat16 bf16;

__device__ __forceinline__ ull pk2(float a, float b) {
    ull r;
    asm("mov.b64 %0, {%1, %2};" : "=l"(r) : "f"(a), "f"(b));
    return r;
}
__device__ __forceinline__ void upk2(ull v, float& a, float& b) {
    asm("mov.b64 {%0, %1}, %2;" : "=f"(a), "=f"(b) : "l"(v));
}
#define FMA2(d, a, b) asm("fma.rn.f32x2 %0, %1, %2, %0;" : "+l"(d) : "l"(a), "l"(b))

__device__ __forceinline__ uint32_t smem_u32(const void* p) {
    uint32_t a;
    asm("{ .reg .u64 t; cvta.to.shared.u64 t, %1; cvt.u32.u64 %0, t; }" : "=r"(a) : "l"(p));
    return a;
}
__device__ __forceinline__ uint32_t pk_bf(bf16 a, bf16 b) {
    uint16_t ra = *(uint16_t*)&a, rb = *(uint16_t*)&b;
    return (uint32_t)ra | ((uint32_t)rb << 16);
}
__device__ __forceinline__ void split_bf(float f, bf16& h, bf16& l) {
    h = __float2bfloat16_rn(f);
    l = __float2bfloat16_rn(f - __bfloat162float(h));
}
__device__ __forceinline__ void split_h(float f, __half& h, __half& l) {
    h = __float2half_rn(f);
    l = __float2half_rn(f - __half2float(h));
}
__device__ __forceinline__ uint32_t cvt_h2(float a, float b) {
    uint32_t r;
    asm("cvt.rn.f16x2.f32 %0, %1, %2;" : "=r"(r) : "f"(b), "f"(a));
    return r;
}
__device__ __forceinline__ uint32_t ex2_h2(uint32_t x) {
    uint32_t r;
    asm("ex2.approx.f16x2 %0, %1;" : "=r"(r) : "r"(x));
    return r;
}
__device__ __forceinline__ uint32_t addh2(uint32_t a, uint32_t b) {
    uint32_t r;
    asm("add.f16x2 %0, %1, %2;" : "=r"(r) : "r"(a), "r"(b));
    return r;
}
__device__ __forceinline__ float h2sum(uint32_t v) {
    __half2 h = *(__half2*)&v;
    return __low2float(h) + __high2float(h);
}

#define LDSM4(r, addr) \
    asm volatile("ldmatrix.sync.aligned.m8n8.x4.shared.b16 {%0,%1,%2,%3}, [%4];" \
                 : "=r"((r)[0]), "=r"((r)[1]), "=r"((r)[2]), "=r"((r)[3]) : "r"(addr))
#define LDSM2(r, addr) \
    asm volatile("ldmatrix.sync.aligned.m8n8.x2.shared.b16 {%0,%1}, [%2];" \
                 : "=r"((r)[0]), "=r"((r)[1]) : "r"(addr))
#define MMA16816(d, a, b) \
    asm volatile("mma.sync.aligned.m16n8k16.row.col.f32.bf16.bf16.f32 " \
                 "{%0,%1,%2,%3}, {%4,%5,%6,%7}, {%8,%9}, {%0,%1,%2,%3};" \
                 : "+f"((d)[0]), "+f"((d)[1]), "+f"((d)[2]), "+f"((d)[3]) \
                 : "r"((a)[0]), "r"((a)[1]), "r"((a)[2]), "r"((a)[3]), \
                   "r"((b)[0]), "r"((b)[1]))
#define MMA16816H(d, a, b) \
    asm volatile("mma.sync.aligned.m16n8k16.row.col.f32.f16.f16.f32 " \
                 "{%0,%1,%2,%3}, {%4,%5,%6,%7}, {%8,%9}, {%0,%1,%2,%3};" \
                 : "+f"((d)[0]), "+f"((d)[1]), "+f"((d)[2]), "+f"((d)[3]) \
                 : "r"((a)[0]), "r"((a)[1]), "r"((a)[2]), "r"((a)[3]), \
                   "r"((b)[0]), "r"((b)[1]))

__device__ __forceinline__ void cpa16(uint32_t saddr, const void* g) {
    asm volatile("cp.async.cg.shared.global [%0], [%1], 16;" :: "r"(saddr), "l"(g));
}
#define CPA_COMMIT() asm volatile("cp.async.commit_group;" ::: "memory")
#define CPA_WAIT(n)  asm volatile("cp.async.wait_group %0;" :: "n"(n) : "memory")

// ------------------------- scratch (device globals, no allocs) -------------
__device__ float g_sf[B_ * N_ * C_];
__device__ float g_aff[B_ * N_ * 64 * 9];
__device__ float g_affsum[B_ * N_ * 9];
__device__ float g_sft_site[B_ * N_ * 9 * C_];
__device__ float g_qkv[B_ * R3C * N_];
__device__ float g_projo[B_ * N_ * C_];
__device__ bf16 g_qkvw_h[R3C * C_], g_qkvw_l[R3C * C_];
__device__ bf16 g_projw_h[C_ * C_], g_projw_l[C_ * C_];
__device__ bf16 g_sftn_h[B_ * N_ * C_], g_sftn_l[B_ * N_ * C_];
__device__ bf16 g_attno_h[B_ * N_ * C_], g_attno_l[B_ * N_ * C_];

// ------------------------- 0) split weights --------------------------------
__global__ void split_w(const float* __restrict__ qkv_w, const float* __restrict__ proj_w) {
    int idx = blockIdx.x * 256 + threadIdx.x;
    for (int i = idx; i < R3C * C_; i += gridDim.x * 256) {
        bf16 h, l;
        split_bf(qkv_w[i], h, l);
        g_qkvw_h[i] = h;
        g_qkvw_l[i] = l;
    }
    for (int i = idx; i < C_ * C_; i += gridDim.x * 256) {
        bf16 h, l;
        split_bf(proj_w[i], h, l);
        g_projw_h[i] = h;
        g_projw_l[i] = l;
    }
}

// ------------------------- 1) 8x8 average pool (float4) --------------------
__global__ void pool_kernel(const float* __restrict__ xs) {
    int y = blockIdx.x, c = blockIdx.y, b = blockIdx.z;
    int t = threadIdx.x;
    int r = t / 28, xx = t - r * 28;
    const float* base = xs + ((size_t)(b * C_ + c) * H_ + (size_t)y * 8) * H_;
    float4 a = *(const float4*)(base + (size_t)r * H_ + xx * 8);
    float4 d = *(const float4*)(base + (size_t)r * H_ + xx * 8 + 4);
    float partial = (a.x + a.y) + (a.z + a.w) + (d.x + d.y) + (d.z + d.w);
    __shared__ float sm[224];
    sm[r * 28 + xx] = partial;
    __syncthreads();
    if (t < HH_) {
        float acc = 0.f;
#pragma unroll
        for (int i = 0; i < 8; i++) acc += sm[i * 28 + t];
        g_sf[((size_t)b * N_ + (size_t)y * HH_ + t) * C_ + c] = acc * (1.0f / 64.0f);
    }
}

// ------------------------- 2) site kernel v6: pixel-pair phase A -----------
#define CK 96
#define PIXPAD 68
#define BUF_F (CK * PIXPAD)
#define S_SF9  (4 * BUF_F)
#define S_STG  (S_SF9 + C_ * 10)
#define S_AFF  (S_STG + 6912)
#define SITE_SMEM_FLOATS (S_AFF + 640)

__global__ __launch_bounds__(384, 1) void site_kernel(const float* __restrict__ xs) {
    extern __shared__ __align__(16) float sm[];
    float* sf9   = sm + S_SF9;
    float* stg   = sm + S_STG;
    float* aff_s = sm + S_AFF;

    int n = blockIdx.x, b = blockIdx.y;
    int y = n / HH_, x = n % HH_;
    int tid = threadIdx.x;
    const float* xbase = xs + ((size_t)b * C_ * H_ + (size_t)y * 8) * H_ + (size_t)x * 8;

    for (int i = tid; i < CK * 16; i += 384) {
        int cl = i >> 4, r = i & 15;
        int py = r >> 1, px4 = (r & 1) << 2;
        cpa16(smem_u32(&sm[cl * PIXPAD + py * 8 + px4]),
              xbase + ((size_t)cl * H_ + py) * H_ + px4);
    }
    CPA_COMMIT();

#pragma unroll
    for (int k = 0; k < 9; k++) {
        int yy = y + k / 3 - 1, xx = x + k % 3 - 1;
        float v = 0.f;
        if (yy >= 0 && yy < HH_ && xx >= 0 && xx < HH_)
            v = g_sf[((size_t)b * N_ + yy * HH_ + xx) * C_ + tid];
        sf9[tid * 10 + k] = v;
    }

    int ppair = tid & 31, csub = tid >> 5;
    int p0 = ppair * 2;
    ull lacc[2][4];
    float lacc8[2];
#pragma unroll
    for (int i = 0; i < 2; i++) {
        lacc8[i] = 0.f;
#pragma unroll
        for (int q = 0; q < 4; q++) lacc[i][q] = 0ull;
    }
    for (int ck = 0; ck < 4; ck++) {
        if (ck < 3) {
            float* nb = sm + (ck + 1) * BUF_F;
            int cbase = (ck + 1) * CK;
            for (int i = tid; i < CK * 16; i += 384) {
                int cl = i >> 4, r = i & 15;
                int py = r >> 1, px4 = (r & 1) << 2;
                cpa16(smem_u32(&nb[cl * PIXPAD + py * 8 + px4]),
                      xbase + ((size_t)(cbase + cl) * H_ + py) * H_ + px4);
            }
            CPA_COMMIT();
            CPA_WAIT(1);
        } else {
            CPA_WAIT(0);
        }
        __syncthreads();
        const float* buf = sm + ck * BUF_F;
#pragma unroll
        for (int cc = 0; cc < 8; cc++) {
            int cl = csub * 8 + cc;
            float2 pv2 = *(const float2*)&buf[cl * PIXPAD + p0];
            float pv[2] = {pv2.x, pv2.y};
            const float* s9 = &sf9[(ck * CK + cl) * 10];
            ull s01 = *(const ull*)(s9 + 0);
            ull s23 = *(const ull*)(s9 + 2);
            ull s45 = *(const ull*)(s9 + 4);
            ull s67 = *(const ull*)(s9 + 6);
            float s8 = s9[8];
#pragma unroll
            for (int i = 0; i < 2; i++) {
                ull pp = pk2(pv[i], pv[i]);
                FMA2(lacc[i][0], pp, s01);
                FMA2(lacc[i][1], pp, s23);
                FMA2(lacc[i][2], pp, s45);
                FMA2(lacc[i][3], pp, s67);
                lacc8[i] = fmaf(pv[i], s8, lacc8[i]);
            }
        }
    }
#pragma unroll
    for (int i = 0; i < 2; i++) {
        float l[9];
        upk2(lacc[i][0], l[0], l[1]);
        upk2(lacc[i][1], l[2], l[3]);
        upk2(lacc[i][2], l[4], l[5]);
        upk2(lacc[i][3], l[6], l[7]);
        l[8] = lacc8[i];
#pragma unroll
        for (int k = 0; k < 9; k++) stg[csub * 576 + (p0 + i) * 9 + k] = l[k];
    }
    __syncthreads();
    for (int idx = tid; idx < 576; idx += 384) {
        float s = 0.f;
#pragma unroll
        for (int ch = 0; ch < 12; ch++) s += stg[ch * 576 + idx];
        int pp = idx / 9, k = idx - pp * 9;
        aff_s[pp * 10 + k] = s * AFF_SCALE;
    }
    __syncthreads();
    if (tid < 64) {
        float m = -1e30f;
#pragma unroll
        for (int k = 0; k < 9; k++) m = fmaxf(m, aff_s[tid * 10 + k]);
        float e[9], ssum = 0.f;
#pragma unroll
        for (int k = 0; k < 9; k++) { e[k] = __expf(aff_s[tid * 10 + k] - m); ssum += e[k]; }
        float inv = 1.f / ssum;
#pragma unroll
        for (int k = 0; k < 9; k++) aff_s[tid * 10 + k] = e[k] * inv;
    }
    __syncthreads();
    size_t abase = ((size_t)b * N_ + n) * 576;
    for (int idx = tid; idx < 576; idx += 384) {
        int pp = idx / 9, k = idx - pp * 9;
        g_aff[abase + idx] = aff_s[pp * 10 + k];
    }
    if (tid < 9) {
        float s = 0.f;
        for (int pp = 0; pp < 64; pp++) s += aff_s[pp * 10 + tid];
        g_affsum[((size_t)b * N_ + n) * 9 + tid] = s;
    }

    int cl_t = tid % 96, psub = tid / 96;
    size_t sbase = ((size_t)b * N_ + n) * 9;
    for (int ck = 0; ck < 4; ck++) {
        const float* buf = sm + ck * BUF_F;
        ull a2[4] = {0, 0, 0, 0};
        float a8 = 0.f;
#pragma unroll
        for (int p4 = 0; p4 < 4; p4++) {
            int pp = psub * 16 + p4 * 4;
            float4 pv4 = *(const float4*)&buf[cl_t * PIXPAD + pp];
            float pv[4] = {pv4.x, pv4.y, pv4.z, pv4.w};
#pragma unroll
            for (int pi = 0; pi < 4; pi++) {
                ull pd = pk2(pv[pi], pv[pi]);
                const float* a9 = &aff_s[(pp + pi) * 10];
                FMA2(a2[0], pd, *(const ull*)(a9 + 0));
                FMA2(a2[1], pd, *(const ull*)(a9 + 2));
                FMA2(a2[2], pd, *(const ull*)(a9 + 4));
                FMA2(a2[3], pd, *(const ull*)(a9 + 6));
                a8 = fmaf(pv[pi], a9[8], a8);
            }
        }
        __syncthreads();
        {
            float r[9];
            upk2(a2[0], r[0], r[1]);
            upk2(a2[1], r[2], r[3]);
            upk2(a2[2], r[4], r[5]);
            upk2(a2[3], r[6], r[7]);
            r[8] = a8;
#pragma unroll
            for (int k = 0; k < 9; k++) stg[psub * 864 + k * 96 + cl_t] = r[k];
        }
        __syncthreads();
        for (int idx = tid; idx < 864; idx += 384) {
            float s = stg[idx] + stg[864 + idx] + stg[1728 + idx] + stg[2592 + idx];
            int k = idx / 96, cl = idx - k * 96;
            g_sft_site[(sbase + k) * C_ + ck * CK + cl] = s;
        }
        __syncthreads();
    }
}

// ------------------------- 3) fold3 gather + normalize + bf16 split --------
__global__ void gather_kernel() {
    int n = blockIdx.x, b = blockIdx.y;
    int y = n / HH_, x = n % HH_;
    int c = threadIdx.x;
    float acc = 0.f, asum = 0.f;
#pragma unroll
    for (int k = 0; k < 9; k++) {
        int i = k / 3, j = k % 3;
        int sy = y + 1 - i, sx = x + 1 - j;
        if (sy >= 0 && sy < HH_ && sx >= 0 && sx < HH_) {
            size_t sb = ((size_t)b * N_ + sy * HH_ + sx) * 9 + k;
            acc += g_sft_site[sb * C_ + c];
            asum += g_affsum[sb];
        }
    }
    float v = acc / (asum + 1e-12f);
    bf16 h, l;
    split_bf(v, h, l);
    size_t o = ((size_t)b * N_ + n) * C_ + c;
    g_sftn_h[o] = h;
    g_sftn_l[o] = l;
}

// ------------------------- 4/6) mma.sync GEMM (all pre-split) --------------
#define SGA 72
#define GEMM_DSMEM (4 * 128 * SGA * 2)
__device__ __forceinline__ int ssw(int m, int n) { return m * 128 + (n ^ (((m >> 2) & 7) << 2)); }

template <bool TRANS_OUT>
__global__ __launch_bounds__(256, 2) void gemm_mma(const float* __restrict__ bias, int R1) {
    extern __shared__ __align__(16) char dyn[];
    bf16* Ah = (bf16*)dyn;
    bf16* Al = Ah + 128 * SGA;
    bf16* Xh = Al + 128 * SGA;
    bf16* Xl = Xh + 128 * SGA;

    int b = blockIdx.z;
    int obase = blockIdx.y * 128;
    int nbase = blockIdx.x * 128;
    int tid = threadIdx.x;
    int lane = tid & 31, w = tid >> 5;
    int wm = w & 3, wn = w >> 2;
    const bf16* Awh = TRANS_OUT ? g_projw_h : g_qkvw_h;
    const bf16* Awl = TRANS_OUT ? g_projw_l : g_qkvw_l;
    const bf16* Xgh = (TRANS_OUT ? g_attno_h : g_sftn_h) + (size_t)b * N_ * C_;
    const bf16* Xgl = (TRANS_OUT ? g_attno_l : g_sftn_l) + (size_t)b * N_ * C_;

    uint32_t baAh = smem_u32(Ah), baAl = smem_u32(Al);
    uint32_t baXh = smem_u32(Xh), baXl = smem_u32(Xl);

    float acc[2][8][4];
#pragma unroll
    for (int i = 0; i < 2; i++)
#pragma unroll
        for (int j = 0; j < 8; j++)
#pragma unroll
            for (int q = 0; q < 4; q++) acc[i][j][q] = 0.f;

    for (int chunk = 0; chunk < 6; chunk++) {
        int kt = chunk * 64;
        __syncthreads();
#pragma unroll
        for (int it = 0; it < 4; it++) {
            int idx = tid + it * 256;
            int row = idx >> 3, g = idx & 7;
            size_t go = (size_t)(obase + row) * C_ + kt + g * 8;
            *(uint4*)(Ah + row * SGA + g * 8) = *(const uint4*)(Awh + go);
            *(uint4*)(Al + row * SGA + g * 8) = *(const uint4*)(Awl + go);
        }
#pragma unroll
        for (int it = 0; it < 4; it++) {
            int idx = tid + it * 256;
            int row = idx >> 3, g = idx & 7;
            uint4 vh = make_uint4(0, 0, 0, 0), vl = make_uint4(0, 0, 0, 0);
            if (nbase + row < N_) {
                size_t go = (size_t)(nbase + row) * C_ + kt + g * 8;
                vh = *(const uint4*)(Xgh + go);
                vl = *(const uint4*)(Xgl + go);
            }
            *(uint4*)(Xh + row * SGA + g * 8) = vh;
            *(uint4*)(Xl + row * SGA + g * 8) = vl;
        }
        __syncthreads();

#pragma unroll
        for (int ks = 0; ks < 4; ks++) {
            int kk = ks * 16;
            uint32_t ah[2][4], al[2][4];
#pragma unroll
            for (int mi = 0; mi < 2; mi++) {
                int r = wm * 32 + mi * 16 + (lane & 15);
                int cofs = kk + ((lane >> 4) << 3);
                uint32_t off = (uint32_t)(r * SGA + cofs) * 2;
                LDSM4(ah[mi], baAh + off);
                LDSM4(al[mi], baAl + off);
            }
#pragma unroll
            for (int ni = 0; ni < 8; ni++) {
                int rn = wn * 64 + ni * 8 + (lane & 7);
                int cofs = kk + (((lane >> 3) & 1) << 3);
                uint32_t off = (uint32_t)(rn * SGA + cofs) * 2;
                uint32_t bh[2], bl[2];
                LDSM2(bh, baXh + off);
                LDSM2(bl, baXl + off);
#pragma unroll
                for (int mi = 0; mi < 2; mi++) {
                    MMA16816(acc[mi][ni], ah[mi], bh);
                    MMA16816(acc[mi][ni], ah[mi], bl);
                    MMA16816(acc[mi][ni], al[mi], bh);
                }
            }
        }
    }
    __syncthreads();

    float* stage = (float*)dyn;
#pragma unroll
    for (int mi = 0; mi < 2; mi++)
#pragma unroll
        for (int ni = 0; ni < 8; ni++) {
            int m = wm * 32 + mi * 16 + (lane >> 2);
            int n = wn * 64 + ni * 8 + ((lane & 3) << 1);
            *(float2*)&stage[ssw(m, n)] = make_float2(acc[mi][ni][0], acc[mi][ni][1]);
            *(float2*)&stage[ssw(m + 8, n)] = make_float2(acc[mi][ni][2], acc[mi][ni][3]);
        }
    __syncthreads();

    if (!TRANS_OUT) {
        float* outp = g_qkv;
        for (int idx = tid; idx < 128 * 32; idx += 256) {
            int m = idx >> 5, nq = (idx & 31) * 4;
            int n0 = nbase + nq;
            if (n0 < N_) {
                float4 v = *(const float4*)&stage[ssw(m, nq)];
                *(float4*)(outp + ((size_t)b * R1 + obase + m) * N_ + n0) = v;
            }
        }
    } else {
        float* outp = g_projo;
        for (int idx = tid; idx < 128 * 32; idx += 256) {
            int n = idx >> 5, mq = (idx & 31) * 4;
            int ng = nbase + n;
            if (ng < N_) {
                int xw = (((mq >> 2) & 7) << 2);
                float4 v;
                v.x = stage[(mq + 0) * 128 + (n ^ xw)] + bias[obase + mq + 0];
                v.y = stage[(mq + 1) * 128 + (n ^ xw)] + bias[obase + mq + 1];
                v.z = stage[(mq + 2) * 128 + (n ^ xw)] + bias[obase + mq + 2];
                v.w = stage[(mq + 3) * 128 + (n ^ xw)] + bias[obase + mq + 3];
                *(float4*)(outp + ((size_t)b * N_ + ng) * C_ + obase + mq) = v;
            }
        }
    }
}

// ------------------------- 5) flash attention: f16x2 exp + f16 PV ----------
#define FQS 56
#define FVS 72
#define FOFF_QH 0
#define FOFF_QL (FOFF_QH + 128 * FQS * 2)
#define FOFF_KH (FOFF_QL + 128 * FQS * 2)
#define FOFF_KL (FOFF_KH + 64 * FQS * 2)
#define FOFF_VH (FOFF_KL + 64 * FQS * 2)
#define FOFF_VL (FOFF_VH + 48 * FVS * 2)
#define FLASH_DSMEM (FOFF_VL + 48 * FVS * 2)

__global__ __launch_bounds__(256, 2) void flash_mma() {
    extern __shared__ __align__(16) char fdyn[];
    bf16*   Qh = (bf16*)(fdyn + FOFF_QH);
    bf16*   Ql = (bf16*)(fdyn + FOFF_QL);
    bf16*   Kh = (bf16*)(fdyn + FOFF_KH);
    bf16*   Kl = (bf16*)(fdyn + FOFF_KL);
    __half* Vh = (__half*)(fdyn + FOFF_VH);
    __half* Vl = (__half*)(fdyn + FOFF_VL);

    int mbase = blockIdx.x * 128, h = blockIdx.y, b = blockIdx.z;
    int tid = threadIdx.x;
    int lane = tid & 31, w = tid >> 5;
    const float* qkb = g_qkv + ((size_t)b * R3C + (size_t)h * (3 * HD)) * N_;

    uint32_t baQh = smem_u32(Qh), baQl = smem_u32(Ql);
    uint32_t baKh = smem_u32(Kh), baKl = smem_u32(Kl);
    uint32_t baVh = smem_u32(Vh), baVl = smem_u32(Vl);

    for (int idx = tid; idx < HD * 128; idx += 256) {
        int d = idx >> 7, m = idx & 127;
        int mg = mbase + m;
        float f = (mg < N_) ? qkb[(size_t)d * N_ + mg] : 0.f;
        bf16 hh, ll;
        split_bf(f, hh, ll);
        Qh[m * FQS + d] = hh;
        Ql[m * FQS + d] = ll;
    }
    __syncthreads();

    uint32_t qh[3][4], ql[3][4];
#pragma unroll
    for (int ks = 0; ks < 3; ks++) {
        int r = w * 16 + (lane & 15);
        int cofs = ks * 16 + ((lane >> 4) << 3);
        uint32_t off = (uint32_t)(r * FQS + cofs) * 2;
        LDSM4(qh[ks], baQh + off);
        LDSM4(ql[ks], baQl + off);
    }

    float mrow[2] = {-1e30f, -1e30f};
    float lrow[2] = {0.f, 0.f};
    float o[6][4];
#pragma unroll
    for (int i = 0; i < 6; i++)
#pragma unroll
        for (int j = 0; j < 4; j++) o[i][j] = 0.f;

    for (int t = 0; t < 13; t++) {
        int kb = t * 64;
        __syncthreads();
        for (int idx = tid; idx < HD * 64; idx += 256) {
            int d = idx >> 6, kk = idx & 63;
            int kg = kb + kk;
            float f = (kg < N_) ? qkb[(size_t)(HD + d) * N_ + kg] : 0.f;
            bf16 hh, ll;
            split_bf(f, hh, ll);
            Kh[kk * FQS + d] = hh;
            Kl[kk * FQS + d] = ll;
        }
        for (int idx = tid; idx < HD * 64; idx += 256) {
            int d = idx >> 6, kk = idx & 63;
            int kg = kb + kk;
            float f = (kg < N_) ? qkb[(size_t)(2 * HD + d) * N_ + kg] : 0.f;
            __half hh, ll;
            split_h(f, hh, ll);
            Vh[d * FVS + kk] = hh;
            Vl[d * FVS + kk] = ll;
        }
        __syncthreads();

        float sacc[8][4];
#pragma unroll
        for (int nb = 0; nb < 8; nb++)
#pragma unroll
            for (int j = 0; j < 4; j++) sacc[nb][j] = 0.f;
#pragma unroll
        for (int ks = 0; ks < 3; ks++) {
#pragma unroll
            for (int nbp = 0; nbp < 4; nbp++) {
                int rn = nbp * 16 + ((lane >> 4) & 1) * 8 + (lane & 7);
                int cofs = ks * 16 + ((lane >> 3) & 1) * 8;
                uint32_t off = (uint32_t)(rn * FQS + cofs) * 2;
                uint32_t kbh[4], kbl[4];
                LDSM4(kbh, baKh + off);
                LDSM4(kbl, baKl + off);
                MMA16816(sacc[2 * nbp], qh[ks], kbh);
                MMA16816(sacc[2 * nbp], qh[ks], kbl);
                MMA16816(sacc[2 * nbp], ql[ks], kbh);
                MMA16816(sacc[2 * nbp + 1], qh[ks], kbh + 2);
                MMA16816(sacc[2 * nbp + 1], qh[ks], kbl + 2);
                MMA16816(sacc[2 * nbp + 1], ql[ks], kbh + 2);
            }
        }

#pragma unroll
        for (int nb = 0; nb < 8; nb++)
#pragma unroll
            for (int j = 0; j < 4; j++) sacc[nb][j] *= ATTN_SCALE;
        if (kb + 64 > N_) {
#pragma unroll
            for (int nb = 0; nb < 8; nb++)
#pragma unroll
                for (int j = 0; j < 4; j++) {
                    int kg = kb + nb * 8 + (lane & 3) * 2 + (j & 1);
                    if (kg >= N_) sacc[nb][j] = -1e30f;
                }
        }

        float mx0 = -1e30f, mx1 = -1e30f;
#pragma unroll
        for (int nb = 0; nb < 8; nb++) {
            mx0 = fmaxf(mx0, fmaxf(sacc[nb][0], sacc[nb][1]));
            mx1 = fmaxf(mx1, fmaxf(sacc[nb][2], sacc[nb][3]));
        }
        mx0 = fmaxf(mx0, __shfl_xor_sync(0xffffffffu, mx0, 1));
        mx0 = fmaxf(mx0, __shfl_xor_sync(0xffffffffu, mx0, 2));
        mx1 = fmaxf(mx1, __shfl_xor_sync(0xffffffffu, mx1, 1));
        mx1 = fmaxf(mx1, __shfl_xor_sync(0xffffffffu, mx1, 2));
        float mn0 = fmaxf(mrow[0], mx0), mn1 = fmaxf(mrow[1], mx1);
        float f0 = __expf(mrow[0] - mn0), f1 = __expf(mrow[1] - mn1);
        mrow[0] = mn0; mrow[1] = mn1;

        float c0 = -mn0 * LOG2E, c1 = -mn1 * LOG2E;
        uint32_t pa[4][4];
        uint32_t sum01 = 0, sum23 = 0;
#pragma unroll
        for (int nb = 0; nb < 8; nb++) {
            float t0 = fmaf(sacc[nb][0], LOG2E, c0);
            float t1 = fmaf(sacc[nb][1], LOG2E, c0);
            float t2 = fmaf(sacc[nb][2], LOG2E, c1);
            float t3 = fmaf(sacc[nb][3], LOG2E, c1);
            uint32_t p01 = ex2_h2(cvt_h2(t0, t1));
            uint32_t p23 = ex2_h2(cvt_h2(t2, t3));
            sum01 = addh2(sum01, p01);
            sum23 = addh2(sum23, p23);
            int ks2 = nb >> 1, ri = (nb & 1) * 2;
            pa[ks2][ri] = p01;
            pa[ks2][ri + 1] = p23;
        }
        float ls0 = h2sum(sum01), ls1 = h2sum(sum23);
        ls0 += __shfl_xor_sync(0xffffffffu, ls0, 1);
        ls0 += __shfl_xor_sync(0xffffffffu, ls0, 2);
        ls1 += __shfl_xor_sync(0xffffffffu, ls1, 1);
        ls1 += __shfl_xor_sync(0xffffffffu, ls1, 2);
        lrow[0] = lrow[0] * f0 + ls0;
        lrow[1] = lrow[1] * f1 + ls1;

#pragma unroll
        for (int db = 0; db < 6; db++) {
            o[db][0] *= f0; o[db][1] *= f0;
            o[db][2] *= f1; o[db][3] *= f1;
        }
#pragma unroll
        for (int ks = 0; ks < 4; ks++) {
#pragma unroll
            for (int dbp = 0; dbp < 3; dbp++) {
                int rn = dbp * 16 + ((lane >> 4) & 1) * 8 + (lane & 7);
                int cofs = ks * 16 + ((lane >> 3) & 1) * 8;
                uint32_t off = (uint32_t)(rn * FVS + cofs) * 2;
                uint32_t vbh[4], vbl[4];
                LDSM4(vbh, baVh + off);
                LDSM4(vbl, baVl + off);
                MMA16816H(o[2 * dbp], pa[ks], vbh);
                MMA16816H(o[2 * dbp], pa[ks], vbl);
                MMA16816H(o[2 * dbp + 1], pa[ks], vbh + 2);
                MMA16816H(o[2 * dbp + 1], pa[ks], vbl + 2);
            }
        }
    }

    __syncthreads();
    float* stage = (float*)fdyn;
    float li0 = 1.f / lrow[0], li1 = 1.f / lrow[1];
    int r = lane >> 2, cq = (lane & 3) * 2;
#pragma unroll
    for (int db = 0; db < 6; db++) {
        int m0 = w * 16 + r;
        *(float2*)&stage[m0 * 52 + db * 8 + cq] = make_float2(o[db][0] * li0, o[db][1] * li0);
        *(float2*)&stage[(m0 + 8) * 52 + db * 8 + cq] = make_float2(o[db][2] * li1, o[db][3] * li1);
    }
    __syncthreads();
    for (int idx = tid; idx < 128 * 12; idx += 256) {
        int m = idx / 12, dq = (idx % 12) * 4;
        int mg = mbase + m;
        if (mg < N_) {
            float4 v = *(const float4*)&stage[m * 52 + dq];
            bf16 h0, l0, h1, l1, h2, l2, h3, l3;
            split_bf(v.x, h0, l0); split_bf(v.y, h1, l1);
            split_bf(v.z, h2, l2); split_bf(v.w, h3, l3);
            size_t go = ((size_t)b * N_ + mg) * C_ + h * HD + dq;
            *(uint2*)(g_attno_h + go) = make_uint2(pk_bf(h0, h1), pk_bf(h2, h3));
            *(uint2*)(g_attno_l + go) = make_uint2(pk_bf(l0, l1), pk_bf(l2, l3));
        }
    }
}

// ------------------------- 7) scatter (float4 stores) ----------------------
__global__ void scatter_kernel(float* __restrict__ out) {
    __shared__ __align__(16) float out9[C_ * 10];
    __shared__ float aff_s[64 * 9];
    int n = blockIdx.x, b = blockIdx.y;
    int y = n / HH_, x = n % HH_;
    int tid = threadIdx.x;

#pragma unroll
    for (int k = 0; k < 9; k++) {
        int yy = y + k / 3 - 1, xx = x + k % 3 - 1;
        float v = 0.f;
        if (yy >= 0 && yy < HH_ && xx >= 0 && xx < HH_)
            v = g_projo[((size_t)b * N_ + yy * HH_ + xx) * C_ + tid];
        out9[tid * 10 + k] = v;
    }
    size_t abase = ((size_t)b * N_ + n) * 576;
    for (int idx = tid; idx < 576; idx += 384) aff_s[idx] = g_aff[abase + idx];
    __syncthreads();

    int pg = tid & 15, cg = tid >> 4;
    int py = pg >> 1, px4 = (pg & 1) * 4;
    int p0 = py * 8 + px4;
    ull av2[4][4];
    float av8[4];
#pragma unroll
    for (int i = 0; i < 4; i++) {
        const float* a = &aff_s[(p0 + i) * 9];
        av2[i][0] = pk2(a[0], a[1]);
        av2[i][1] = pk2(a[2], a[3]);
        av2[i][2] = pk2(a[4], a[5]);
        av2[i][3] = pk2(a[6], a[7]);
        av8[i] = a[8];
    }
    float* obase = out + ((size_t)b * C_ * H_ + (size_t)(y * 8 + py)) * H_ + (size_t)x * 8 + px4;
    for (int c = cg; c < C_; c += 24) {
        const float* o9 = &out9[c * 10];
        ull o01 = *(const ull*)(o9 + 0);
        ull o23 = *(const ull*)(o9 + 2);
        ull o45 = *(const ull*)(o9 + 4);
        ull o67 = *(const ull*)(o9 + 6);
        float o8 = o9[8];
        float res[4];
#pragma unroll
        for (int i = 0; i < 4; i++) {
            ull acc2 = 0ull;
            FMA2(acc2, av2[i][0], o01);
            FMA2(acc2, av2[i][1], o23);
            FMA2(acc2, av2[i][2], o45);
            FMA2(acc2, av2[i][3], o67);
            float lo, hi;
            upk2(acc2, lo, hi);
            res[i] = lo + hi + av8[i] * o8;
        }
        *(float4*)(obase + (size_t)c * H_ * H_) = make_float4(res[0], res[1], res[2], res[3]);
    }
}

// ------------------------- launch ------------------------------------------
extern "C" void kernel_launch(void* const* d_in, const int* in_sizes, int n_in,
                              void* d_out, int out_size) {
    const float* xs     = (const float*)d_in[0];
    const float* qkv_w  = (const float*)d_in[2];
    const float* proj_w = (const float*)d_in[3];
    const float* proj_b = (const float*)d_in[4];
    float* out = (float*)d_out;

    cudaFuncSetAttribute(site_kernel, cudaFuncAttributeMaxDynamicSharedMemorySize,
                         SITE_SMEM_FLOATS * (int)sizeof(float));
    cudaFuncSetAttribute(flash_mma, cudaFuncAttributeMaxDynamicSharedMemorySize, FLASH_DSMEM);
    cudaFuncSetAttribute(gemm_mma<false>, cudaFuncAttributeMaxDynamicSharedMemorySize, GEMM_DSMEM);
    cudaFuncSetAttribute(gemm_mma<true>, cudaFuncAttributeMaxDynamicSharedMemorySize, GEMM_DSMEM);

    split_w<<<144, 256>>>(qkv_w, proj_w);
    pool_kernel<<<dim3(HH_, C_, B_), 224>>>(xs);
    site_kernel<<<dim3(N_, B_), 384, SITE_SMEM_FLOATS * sizeof(float)>>>(xs);
    gather_kernel<<<dim3(N_, B_), C_>>>();
    gemm_mma<false><<<dim3(7, 9, B_), 256, GEMM_DSMEM>>>(nullptr, R3C);
    flash_mma<<<dim3(7, HEADS, B_), 256, FLASH_DSMEM>>>();
    gemm_mma<true><<<dim3(7, 3, B_), 256, GEMM_DSMEM>>>(proj_b, C_);
    scatter_kernel<<<dim3(N_, B_), 384>>>(out);
}